// round 12
// baseline (speedup 1.0000x reference)
#include <cuda_runtime.h>
#include <cuda_bf16.h>
#include <cstdint>

// Problem constants (fixed-shape problem)
#define BB 4
#define TT 12
#define NN 10000
#define FF 32
#define EE 160000
#define MM (BB*NN)          // 40000 rows
#define SLICES (BB*TT)      // 48
#define SL (NN*FF)          // 320000 elements per slice
#define SL2 (SL/2)          // slice stride in float2/ull units
#define SCAL_ROWS 20032     // rows handled by scalar role (626 blocks * 32)

typedef unsigned long long ull;

// -------- device scratch (static, no allocation; zero-initialized) --------
__device__ float d_XA[SLICES * NN * FF];   // aggregated features (61.4MB)
__device__ float d_deg[NN];
__device__ float d_dinv[NN];
__device__ int   d_cnt[NN];
__device__ int   d_fill[NN];
__device__ int   d_rowptr[NN + 1];
__device__ int2  d_csrp[EE];               // packed {src_row, weight_bits}
__device__ float d_bf[96];                 // folded biases z|r|h
__device__ float d_probs[TT];
// scalar-path weights
__device__ float d_Wpack[32 * 32 * 4];     // [k][j][{Wz',Wr',Wh',Uz}]
__device__ float d_Ur[1024];
__device__ float d_Uh[1024];
// mma-path fragment-ordered bf16x2 weights: [term][nt][kt][lane][reg]
__device__ uint32_t d_fB1[2 * 12 * 4 * 32 * 2];   // gates B: K=64, N=96
__device__ uint32_t d_fUh[2 * 4 * 2 * 32 * 2];    // Uh:      K=32, N=32
__device__ uint32_t d_fLn[2 * 4 * 2 * 32 * 2];    // lin_w:   K=32, N=32

// ===================== f32x2 helpers =====================
__device__ __forceinline__ void fma2(ull& d, ull a, ull b) {
    asm("fma.rn.f32x2 %0, %1, %2, %0;" : "+l"(d) : "l"(a), "l"(b));
}
__device__ __forceinline__ void mul2(ull& d, ull a, ull b) {
    asm("mul.rn.f32x2 %0, %1, %2;" : "=l"(d) : "l"(a), "l"(b));
}
__device__ __forceinline__ ull splat2(float w) {
    ull r; asm("mov.b64 %0, {%1, %1};" : "=l"(r) : "f"(w)); return r;
}
__device__ __forceinline__ float2 unpk(ull a) {
    float2 f; asm("mov.b64 {%0, %1}, %2;" : "=f"(f.x), "=f"(f.y) : "l"(a)); return f;
}

// ===================== bf16 split/pack helpers =====================
__device__ __forceinline__ uint32_t packbf(float a, float b) {
    uint32_t r;
    asm("cvt.rn.bf16x2.f32 %0, %1, %2;" : "=r"(r) : "f"(b), "f"(a));
    return r;
}
__device__ __forceinline__ void split2(float a, float b, uint32_t& hi, uint32_t& lo) {
    hi = packbf(a, b);
    float ha = __uint_as_float(hi << 16);
    float hb = __uint_as_float(hi & 0xffff0000u);
    lo = packbf(a - ha, b - hb);
}
__device__ __forceinline__ void mma16816(float* d, const uint32_t* a,
                                         uint32_t b0, uint32_t b1) {
    asm("mma.sync.aligned.m16n8k16.row.col.f32.bf16.bf16.f32 "
        "{%0,%1,%2,%3}, {%4,%5,%6,%7}, {%8,%9}, {%0,%1,%2,%3};"
        : "+f"(d[0]), "+f"(d[1]), "+f"(d[2]), "+f"(d[3])
        : "r"(a[0]), "r"(a[1]), "r"(a[2]), "r"(a[3]), "r"(b0), "r"(b1));
}

// -------- degree/count accumulation --------
__global__ void k_degcnt(const int* ei, const float* ew) {
    int e = blockIdx.x * blockDim.x + threadIdx.x;
    if (e >= EE) return;
    int col = ei[EE + e];
    atomicAdd(&d_deg[col], ew[e]);
    atomicAdd(&d_cnt[col], 1);
}

__device__ __forceinline__ float b1elem(int k, int j,
        const float* Wz, const float* lzw, const float* Wr, const float* lrw,
        const float* Wh, const float* lhw) {
    int g = j >> 5, jj = j & 31;
    if (k < 32) {
        const float* Wg = (g == 0) ? Wz : (g == 1) ? Wr : Wh;
        const float* Lg = (g == 0) ? lzw : (g == 1) ? lrw : lhw;
        float s = 0.f;
        #pragma unroll
        for (int m = 0; m < 32; m++) s += Wg[k * 32 + m] * Lg[m * 32 + jj];
        return s;
    }
    return (g == 0) ? lzw[k * 32 + jj] : (g == 1) ? lrw[k * 32 + jj] : 0.f;
}

// single-block prep: both weight formats + dinv + scan + softmax + re-zero
__global__ void k_scan_prep(const float* att,
                            const float* Wz, const float* bz, const float* lzw, const float* lzb,
                            const float* Wr, const float* br, const float* lrw, const float* lrb,
                            const float* Wh, const float* bh, const float* lhw, const float* lhb,
                            const float* linw) {
    int tid = threadIdx.x;
    int lane = tid & 31;

    // ---- scalar-path packed weights ----
    {
        const float* Ws[3]  = {Wz, Wr, Wh};
        const float* ls[3]  = {lzw, lrw, lhw};
        int k = tid >> 5, j = tid & 31;
        #pragma unroll
        for (int g = 0; g < 3; g++) {
            float s = 0.f;
            #pragma unroll
            for (int m = 0; m < 32; m++) s += Ws[g][k * 32 + m] * ls[g][m * 32 + j];
            d_Wpack[(k * 32 + j) * 4 + g] = s;
        }
        d_Wpack[(k * 32 + j) * 4 + 3] = lzw[(32 + k) * 32 + j];  // Uz
        d_Ur[k * 32 + j] = lrw[(32 + k) * 32 + j];
        d_Uh[k * 32 + j] = lhw[(32 + k) * 32 + j];
    }
    // ---- mma-path B1 fragments ----
    for (int i = tid; i < 12 * 4 * 32; i += 1024) {
        int nt = i >> 7;
        int kt = (i >> 5) & 3;
        int ln = i & 31;
        int n = nt * 8 + (ln >> 2);
        int kb = kt * 16 + (ln & 3) * 2;
        #pragma unroll
        for (int r = 0; r < 2; r++) {
            int k0 = kb + r * 8;
            float w0 = b1elem(k0, n, Wz, lzw, Wr, lrw, Wh, lhw);
            float w1 = b1elem(k0 + 1, n, Wz, lzw, Wr, lrw, Wh, lhw);
            uint32_t hi, lo;
            split2(w0, w1, hi, lo);
            d_fB1[((0 * 12 + nt) * 4 + kt) * 64 + ln * 2 + r] = hi;
            d_fB1[((1 * 12 + nt) * 4 + kt) * 64 + ln * 2 + r] = lo;
        }
    }
    // ---- mma-path Uh + Ln fragments ----
    for (int i = tid; i < 4 * 2 * 32; i += 1024) {
        int nt = i >> 6;
        int kt = (i >> 5) & 1;
        int ln = i & 31;
        int n = nt * 8 + (ln >> 2);
        int kb = kt * 16 + (ln & 3) * 2;
        #pragma unroll
        for (int r = 0; r < 2; r++) {
            int k0 = kb + r * 8;
            float u0 = lhw[(32 + k0) * 32 + n];
            float u1 = lhw[(32 + k0 + 1) * 32 + n];
            float l0 = linw[k0 * 32 + n];
            float l1 = linw[(k0 + 1) * 32 + n];
            uint32_t hi, lo;
            split2(u0, u1, hi, lo);
            d_fUh[((0 * 4 + nt) * 2 + kt) * 64 + ln * 2 + r] = hi;
            d_fUh[((1 * 4 + nt) * 2 + kt) * 64 + ln * 2 + r] = lo;
            split2(l0, l1, hi, lo);
            d_fLn[((0 * 4 + nt) * 2 + kt) * 64 + ln * 2 + r] = hi;
            d_fLn[((1 * 4 + nt) * 2 + kt) * 64 + ln * 2 + r] = lo;
        }
    }
    // ---- folded biases + softmax ----
    if (tid < 96) {
        int g = tid >> 5; int jj = tid & 31;
        const float* bs = (g == 0) ? bz : (g == 1) ? br : bh;
        const float* ls = (g == 0) ? lzw : (g == 1) ? lrw : lhw;
        const float* lb = (g == 0) ? lzb : (g == 1) ? lrb : lhb;
        float s = lb[jj];
        for (int m = 0; m < 32; m++) s += bs[m] * ls[m * 32 + jj];
        d_bf[g * 32 + jj] = s;
    }
    if (tid == 0) {
        float mx = -1e30f;
        for (int i = 0; i < TT; i++) mx = fmaxf(mx, att[i]);
        float e[TT]; float sum = 0.f;
        for (int i = 0; i < TT; i++) { e[i] = expf(att[i] - mx); sum += e[i]; }
        for (int i = 0; i < TT; i++) d_probs[i] = e[i] / sum;
    }
    // ---- dinv ----
    for (int i = tid; i < NN; i += 1024) {
        float d = d_deg[i] + 1.0f;
        d_dinv[i] = rsqrtf(fmaxf(d, 1e-12f));
    }
    // ---- 3-level exclusive scan ----
    __shared__ int warpsum[32];
    int v[10];
    int s = 0;
    int base = tid * 10;
    if (tid < 1000) {
        #pragma unroll
        for (int u = 0; u < 10; u++) { v[u] = s; s += d_cnt[base + u]; }
    }
    int inc = s;
    #pragma unroll
    for (int o = 1; o < 32; o <<= 1) {
        int t = __shfl_up_sync(0xffffffffu, inc, o);
        if (lane >= o) inc += t;
    }
    if (lane == 31) warpsum[tid >> 5] = inc;
    __syncthreads();
    if (tid < 32) {
        int ws = warpsum[tid];
        int winc = ws;
        #pragma unroll
        for (int o = 1; o < 32; o <<= 1) {
            int t = __shfl_up_sync(0xffffffffu, winc, o);
            if (lane >= o) winc += t;
        }
        warpsum[tid] = winc - ws;
    }
    __syncthreads();
    int texcl = warpsum[tid >> 5] + inc - s;
    if (tid < 1000) {
        #pragma unroll
        for (int u = 0; u < 10; u++) d_rowptr[base + u] = texcl + v[u];
    }
    if (tid == 1000) d_rowptr[NN] = texcl;

    __syncthreads();
    for (int i = tid; i < NN; i += 1024) { d_deg[i] = 0.f; d_cnt[i] = 0; d_fill[i] = 0; }
}

__global__ void k_fill(const int* ei, const float* ew) {
    int e = blockIdx.x * blockDim.x + threadIdx.x;
    if (e >= EE) return;
    int r = ei[e];
    int c = ei[EE + e];
    int pos = d_rowptr[c] + atomicAdd(&d_fill[c], 1);
    float w = d_dinv[r] * ew[e] * d_dinv[c];
    d_csrp[pos] = make_int2(r, __float_as_int(w));
}

// -------- aggregation (unchanged, at its L2 floor) --------
__global__ void __launch_bounds__(256) k_agg(const float* __restrict__ x) {
    int w = (blockIdx.x * blockDim.x + threadIdx.x) >> 5;
    int lane = threadIdx.x & 31;
    if (w >= NN * 6) return;
    int g = w / NN;
    int n = w - g * NN;
    int half = lane >> 4;
    int fp = lane & 15;

    const ull* px = (const ull*)x;
    int sbase = g * 8 + half;
    long ofs0 = (long)(sbase + 0) * SL2 + fp;
    long ofs1 = (long)(sbase + 2) * SL2 + fp;
    long ofs2 = (long)(sbase + 4) * SL2 + fp;
    long ofs3 = (long)(sbase + 6) * SL2 + fp;

    float dn = d_dinv[n];
    ull selfw2 = splat2(dn * dn);
    ull acc0, acc1, acc2, acc3;
    {
        int r16 = n * 16;
        mul2(acc0, __ldg(px + ofs0 + r16), selfw2);
        mul2(acc1, __ldg(px + ofs1 + r16), selfw2);
        mul2(acc2, __ldg(px + ofs2 + r16), selfw2);
        mul2(acc3, __ldg(px + ofs3 + r16), selfw2);
    }
    int e0 = d_rowptr[n], e1 = d_rowptr[n + 1];
    int2 ed;
    if (e0 < e1) ed = __ldg(&d_csrp[e0]);
    for (int e = e0; e < e1; e++) {
        int2 edn;
        if (e + 1 < e1) edn = __ldg(&d_csrp[e + 1]);
        ull w2 = splat2(__int_as_float(ed.y));
        int r16 = ed.x * 16;
        ull v0 = __ldg(px + ofs0 + r16);
        ull v1 = __ldg(px + ofs1 + r16);
        ull v2 = __ldg(px + ofs2 + r16);
        ull v3 = __ldg(px + ofs3 + r16);
        fma2(acc0, v0, w2);
        fma2(acc1, v1, w2);
        fma2(acc2, v2, w2);
        fma2(acc3, v3, w2);
        ed = edn;
    }
    float2* po = (float2*)d_XA;
    int n16 = n * 16 + fp;
    __stcs(po + (long)(sbase + 0) * SL2 + n16, unpk(acc0));
    __stcs(po + (long)(sbase + 2) * SL2 + n16, unpk(acc1));
    __stcs(po + (long)(sbase + 4) * SL2 + n16, unpk(acc2));
    __stcs(po + (long)(sbase + 6) * SL2 + n16, unpk(acc3));
}

// ==================== HYBRID GRU: scalar-FMA blocks ∥ warp-MMA blocks ====
// b%3<2 -> scalar role (32 rows, FMA pipe); b%3==2 -> mma role (64 rows,
// tensor pipe). %3 interleave puts a 2:1 mix on every SM so both pipes run.
union SmemU {
    struct {
        float W4[4096]; float Ur[1024]; float Uh[1024];
        float b[96]; float prob[16];
        float stg[4][3][256];
    } s;
    struct {
        uint32_t B1[6144]; uint32_t Uh2[1024]; uint32_t Ln[1024];
        float bias[96]; float prob[16];
    } m;
};

__global__ void __launch_bounds__(128)
k_ghyb(const float* __restrict__ linw, const float* __restrict__ linb,
       float* __restrict__ out) {
    __shared__ SmemU su;
    int tid = threadIdx.x;
    int bid = blockIdx.x;
    int role = (bid % 3) == 2;            // 0=scalar, 1=mma
    int lane = tid & 31;
    int w = tid >> 5;

    if (!role) {
        // ================== scalar f32x2 role (rows 0..SCAL_ROWS) ==========
        for (int i = tid; i < 4096; i += 128) su.s.W4[i] = d_Wpack[i];
        for (int i = tid; i < 1024; i += 128) {
            su.s.Ur[i] = d_Ur[i]; su.s.Uh[i] = d_Uh[i];
        }
        if (tid < 96) su.s.b[tid] = d_bf[tid];
        if (tid < TT) su.s.prob[tid] = d_probs[tid];
        __syncthreads();

        int si = (bid / 3) * 2 + (bid % 3);
        int m0 = si * 32 + w * 8;
        int j = lane;
        float* xaT = su.s.stg[w][0];
        float* hT  = su.s.stg[w][1];
        float* hrT = su.s.stg[w][2];

        int b = m0 / NN;
        int base = b * (TT * SL) + (m0 - b * NN) * 32 + j;

        float h[8], hacc[8], xan[8];
        #pragma unroll
        for (int r = 0; r < 8; r++) {
            h[r] = 0.f; hacc[r] = 0.f;
            xan[r] = __ldg(&d_XA[base + r * 32]);
        }
        ull bz2 = splat2(su.s.b[j]), br2 = splat2(su.s.b[32 + j]), bh2 = splat2(su.s.b[64 + j]);

        for (int t = 0; t < TT; t++) {
            float xa[8];
            #pragma unroll
            for (int r = 0; r < 8; r++) xa[r] = xan[r];
            if (t + 1 < TT) {
                #pragma unroll
                for (int r = 0; r < 8; r++)
                    xan[r] = __ldg(&d_XA[base + (t + 1) * SL + r * 32]);
            }
            __syncwarp();
            ((float4*)(xaT + j * 8))[0] = make_float4(xa[0], xa[1], xa[2], xa[3]);
            ((float4*)(xaT + j * 8))[1] = make_float4(xa[4], xa[5], xa[6], xa[7]);
            ((float4*)(hT  + j * 8))[0] = make_float4(h[0], h[1], h[2], h[3]);
            ((float4*)(hT  + j * 8))[1] = make_float4(h[4], h[5], h[6], h[7]);
            __syncwarp();

            ull az[4], ar[4], ah[4];
            #pragma unroll
            for (int p = 0; p < 4; p++) { az[p] = bz2; ar[p] = br2; ah[p] = bh2; }

            #pragma unroll 4
            for (int k = 0; k < 32; k++) {
                ulonglong2 x01 = ((const ulonglong2*)(xaT + k * 8))[0];
                ulonglong2 x23 = ((const ulonglong2*)(xaT + k * 8))[1];
                ulonglong2 h01 = ((const ulonglong2*)(hT  + k * 8))[0];
                ulonglong2 h23 = ((const ulonglong2*)(hT  + k * 8))[1];
                float4 w4 = ((const float4*)su.s.W4)[k * 32 + j];
                float urv = su.s.Ur[k * 32 + j];
                ull wz2 = splat2(w4.x), wr2 = splat2(w4.y), wh2 = splat2(w4.z);
                ull uz2 = splat2(w4.w), ur2 = splat2(urv);
                ull xp[4] = {x01.x, x01.y, x23.x, x23.y};
                ull hp[4] = {h01.x, h01.y, h23.x, h23.y};
                #pragma unroll
                for (int p = 0; p < 4; p++) {
                    fma2(az[p], xp[p], wz2); fma2(az[p], hp[p], uz2);
                    fma2(ar[p], xp[p], wr2); fma2(ar[p], hp[p], ur2);
                    fma2(ah[p], xp[p], wh2);
                }
            }

            float z[8], hr[8];
            #pragma unroll
            for (int p = 0; p < 4; p++) {
                float2 a = unpk(az[p]);
                float2 b2 = unpk(ar[p]);
                z[2 * p]     = 1.f / (1.f + __expf(-a.x));
                z[2 * p + 1] = 1.f / (1.f + __expf(-a.y));
                hr[2 * p]     = h[2 * p]     * (1.f / (1.f + __expf(-b2.x)));
                hr[2 * p + 1] = h[2 * p + 1] * (1.f / (1.f + __expf(-b2.y)));
            }
            __syncwarp();
            ((float4*)(hrT + j * 8))[0] = make_float4(hr[0], hr[1], hr[2], hr[3]);
            ((float4*)(hrT + j * 8))[1] = make_float4(hr[4], hr[5], hr[6], hr[7]);
            __syncwarp();

            #pragma unroll 4
            for (int k = 0; k < 32; k++) {
                ulonglong2 r01 = ((const ulonglong2*)(hrT + k * 8))[0];
                ulonglong2 r23 = ((const ulonglong2*)(hrT + k * 8))[1];
                ull uh2 = splat2(su.s.Uh[k * 32 + j]);
                fma2(ah[0], r01.x, uh2); fma2(ah[1], r01.y, uh2);
                fma2(ah[2], r23.x, uh2); fma2(ah[3], r23.y, uh2);
            }

            float pt = su.s.prob[t];
            #pragma unroll
            for (int p = 0; p < 4; p++) {
                float2 a = unpk(ah[p]);
                float ht0 = 2.f / (1.f + __expf(-2.f * a.x)) - 1.f;
                float ht1 = 2.f / (1.f + __expf(-2.f * a.y)) - 1.f;
                int r0 = 2 * p, r1 = 2 * p + 1;
                h[r0] = z[r0] * h[r0] + (1.f - z[r0]) * ht0;
                h[r1] = z[r1] * h[r1] + (1.f - z[r1]) * ht1;
                hacc[r0] += pt * h[r0];
                hacc[r1] += pt * h[r1];
            }
        }

        __syncwarp();
        ((float4*)(xaT + j * 8))[0] = make_float4(fmaxf(hacc[0], 0.f), fmaxf(hacc[1], 0.f),
                                                  fmaxf(hacc[2], 0.f), fmaxf(hacc[3], 0.f));
        ((float4*)(xaT + j * 8))[1] = make_float4(fmaxf(hacc[4], 0.f), fmaxf(hacc[5], 0.f),
                                                  fmaxf(hacc[6], 0.f), fmaxf(hacc[7], 0.f));
        __syncwarp();

        ull lb2 = splat2(__ldg(&linb[j]));
        ull acc[4] = {lb2, lb2, lb2, lb2};
        #pragma unroll 4
        for (int k = 0; k < 32; k++) {
            ulonglong2 v01 = ((const ulonglong2*)(xaT + k * 8))[0];
            ulonglong2 v23 = ((const ulonglong2*)(xaT + k * 8))[1];
            ull lw2 = splat2(__ldg(&linw[k * 32 + j]));
            fma2(acc[0], v01.x, lw2); fma2(acc[1], v01.y, lw2);
            fma2(acc[2], v23.x, lw2); fma2(acc[3], v23.y, lw2);
        }
        #pragma unroll
        for (int p = 0; p < 4; p++) {
            float2 a = unpk(acc[p]);
            out[(m0 + 2 * p) * 32 + j] = a.x;
            out[(m0 + 2 * p + 1) * 32 + j] = a.y;
        }
        return;
    }

    // ================== warp-MMA role (rows SCAL_ROWS..MM) ==================
    for (int i = tid; i < 6144; i += 128) su.m.B1[i] = d_fB1[i];
    for (int i = tid; i < 1024; i += 128) { su.m.Uh2[i] = d_fUh[i]; su.m.Ln[i] = d_fLn[i]; }
    if (tid < 96) su.m.bias[tid] = d_bf[tid];
    if (tid < TT) su.m.prob[tid] = d_probs[tid];
    __syncthreads();

    int mi = bid / 3;
    int mblk = SCAL_ROWS + mi * 64;
    if (mblk >= MM) return;                    // tail block fully out of range
    int m0 = mblk + w * 16;
    int b = m0 / NN;
    long base = (long)b * (TT * SL) + (long)(m0 - b * NN) * 32;
    int r1 = lane >> 2;
    int c0 = (lane & 3) * 2;
    const float* xr1 = d_XA + base + (long)r1 * 32 + c0;
    const float* xr2 = xr1 + 8 * 32;

    float h[16], hacc[16];
    #pragma unroll
    for (int j = 0; j < 16; j++) { h[j] = 0.f; hacc[j] = 0.f; }

    for (int t = 0; t < TT; t++) {
        float2 x1[4], x2[4];
        #pragma unroll
        for (int q = 0; q < 4; q++) {
            x1[q] = __ldg((const float2*)(xr1 + (long)t * SL + 8 * q));
            x2[q] = __ldg((const float2*)(xr2 + (long)t * SL + 8 * q));
        }
        uint32_t ahi[4][4], alo[4][4];
        #pragma unroll
        for (int kt = 0; kt < 2; kt++) {
            split2(x1[2 * kt].x,     x1[2 * kt].y,     ahi[kt][0], alo[kt][0]);
            split2(x2[2 * kt].x,     x2[2 * kt].y,     ahi[kt][1], alo[kt][1]);
            split2(x1[2 * kt + 1].x, x1[2 * kt + 1].y, ahi[kt][2], alo[kt][2]);
            split2(x2[2 * kt + 1].x, x2[2 * kt + 1].y, ahi[kt][3], alo[kt][3]);
        }
        #pragma unroll
        for (int kt = 2; kt < 4; kt++) {
            int hn = 2 * (kt - 2);
            split2(h[hn * 4 + 0],       h[hn * 4 + 1],       ahi[kt][0], alo[kt][0]);
            split2(h[hn * 4 + 2],       h[hn * 4 + 3],       ahi[kt][1], alo[kt][1]);
            split2(h[(hn + 1) * 4 + 0], h[(hn + 1) * 4 + 1], ahi[kt][2], alo[kt][2]);
            split2(h[(hn + 1) * 4 + 2], h[(hn + 1) * 4 + 3], ahi[kt][3], alo[kt][3]);
        }

        float z[16], hr[16];
        #pragma unroll
        for (int nt = 0; nt < 8; nt++) {
            float d[4];
            #pragma unroll
            for (int i = 0; i < 4; i++) d[i] = su.m.bias[8 * nt + c0 + (i & 1)];
            #pragma unroll
            for (int kt = 0; kt < 4; kt++) {
                uint2 bh = *(const uint2*)&su.m.B1[((0 * 12 + nt) * 4 + kt) * 64 + lane * 2];
                uint2 bl = *(const uint2*)&su.m.B1[((1 * 12 + nt) * 4 + kt) * 64 + lane * 2];
                mma16816(d, ahi[kt], bh.x, bh.y);
                mma16816(d, ahi[kt], bl.x, bl.y);
                mma16816(d, alo[kt], bh.x, bh.y);
            }
            if (nt < 4) {
                #pragma unroll
                for (int i = 0; i < 4; i++)
                    z[nt * 4 + i] = 1.f / (1.f + __expf(-d[i]));
            } else {
                int hn = nt - 4;
                #pragma unroll
                for (int i = 0; i < 4; i++) {
                    float rg = 1.f / (1.f + __expf(-d[i]));
                    hr[hn * 4 + i] = h[hn * 4 + i] * rg;
                }
            }
        }
        uint32_t rhi[2][4], rlo[2][4];
        #pragma unroll
        for (int kt = 0; kt < 2; kt++) {
            int hn = 2 * kt;
            split2(hr[hn * 4 + 0],       hr[hn * 4 + 1],       rhi[kt][0], rlo[kt][0]);
            split2(hr[hn * 4 + 2],       hr[hn * 4 + 3],       rhi[kt][1], rlo[kt][1]);
            split2(hr[(hn + 1) * 4 + 0], hr[(hn + 1) * 4 + 1], rhi[kt][2], rlo[kt][2]);
            split2(hr[(hn + 1) * 4 + 2], hr[(hn + 1) * 4 + 3], rhi[kt][3], rlo[kt][3]);
        }

        float pt = su.m.prob[t];
        #pragma unroll
        for (int nt = 8; nt < 12; nt++) {
            float d[4];
            #pragma unroll
            for (int i = 0; i < 4; i++) d[i] = su.m.bias[8 * nt + c0 + (i & 1)];
            #pragma unroll
            for (int kt = 0; kt < 4; kt++) {
                uint2 bh = *(const uint2*)&su.m.B1[((0 * 12 + nt) * 4 + kt) * 64 + lane * 2];
                uint2 bl = *(const uint2*)&su.m.B1[((1 * 12 + nt) * 4 + kt) * 64 + lane * 2];
                mma16816(d, ahi[kt], bh.x, bh.y);
                mma16816(d, ahi[kt], bl.x, bl.y);
                mma16816(d, alo[kt], bh.x, bh.y);
            }
            int un = nt - 8;
            #pragma unroll
            for (int kt = 0; kt < 2; kt++) {
                uint2 bh = *(const uint2*)&su.m.Uh2[((0 * 4 + un) * 2 + kt) * 64 + lane * 2];
                uint2 bl = *(const uint2*)&su.m.Uh2[((1 * 4 + un) * 2 + kt) * 64 + lane * 2];
                mma16816(d, rhi[kt], bh.x, bh.y);
                mma16816(d, rhi[kt], bl.x, bl.y);
                mma16816(d, rlo[kt], bh.x, bh.y);
            }
            #pragma unroll
            for (int i = 0; i < 4; i++) {
                int j = un * 4 + i;
                float ht = 2.f / (1.f + __expf(-2.f * d[i])) - 1.f;
                h[j] = z[j] * h[j] + (1.f - z[j]) * ht;
                hacc[j] += pt * h[j];
            }
        }
    }

    uint32_t rhi[2][4], rlo[2][4];
    #pragma unroll
    for (int kt = 0; kt < 2; kt++) {
        int hn = 2 * kt;
        split2(fmaxf(hacc[hn * 4 + 0], 0.f),       fmaxf(hacc[hn * 4 + 1], 0.f),       rhi[kt][0], rlo[kt][0]);
        split2(fmaxf(hacc[hn * 4 + 2], 0.f),       fmaxf(hacc[hn * 4 + 3], 0.f),       rhi[kt][1], rlo[kt][1]);
        split2(fmaxf(hacc[(hn + 1) * 4 + 0], 0.f), fmaxf(hacc[(hn + 1) * 4 + 1], 0.f), rhi[kt][2], rlo[kt][2]);
        split2(fmaxf(hacc[(hn + 1) * 4 + 2], 0.f), fmaxf(hacc[(hn + 1) * 4 + 3], 0.f), rhi[kt][3], rlo[kt][3]);
    }
    #pragma unroll
    for (int nt = 0; nt < 4; nt++) {
        float d[4];
        float lb0 = __ldg(&linb[8 * nt + c0]);
        float lb1 = __ldg(&linb[8 * nt + c0 + 1]);
        d[0] = lb0; d[1] = lb1; d[2] = lb0; d[3] = lb1;
        #pragma unroll
        for (int kt = 0; kt < 2; kt++) {
            uint2 bh = *(const uint2*)&su.m.Ln[((0 * 4 + nt) * 2 + kt) * 64 + lane * 2];
            uint2 bl = *(const uint2*)&su.m.Ln[((1 * 4 + nt) * 2 + kt) * 64 + lane * 2];
            mma16816(d, rhi[kt], bh.x, bh.y);
            mma16816(d, rhi[kt], bl.x, bl.y);
            mma16816(d, rlo[kt], bh.x, bh.y);
        }
        *(float2*)(out + (long)(m0 + r1) * 32 + 8 * nt + c0)     = make_float2(d[0], d[1]);
        *(float2*)(out + (long)(m0 + r1 + 8) * 32 + 8 * nt + c0) = make_float2(d[2], d[3]);
    }
}

extern "C" void kernel_launch(void* const* d_in, const int* in_sizes, int n_in,
                              void* d_out, int out_size) {
    const float* x  = (const float*)d_in[0];
    const int*   ei = (const int*)d_in[1];
    const float* ew = (const float*)d_in[2];

    int iWz, iBz, iLzw, iLzb, iWr, iBr, iLrw, iLrb, iWh, iBh, iLhw, iLhb;
    if (in_sizes[5] == 2048) {
        iWz = 3; iBz = 4; iLzw = 5;  iLzb = 6;
        iWr = 7; iBr = 8; iLrw = 9;  iLrb = 10;
        iWh = 11; iBh = 12; iLhw = 13; iLhb = 14;
    } else {
        iWz = 3; iBz = 4; iWr = 5; iBr = 6; iWh = 7; iBh = 8;
        iLzw = 9; iLzb = 10; iLrw = 11; iLrb = 12; iLhw = 13; iLhb = 14;
    }
    const float* Wz  = (const float*)d_in[iWz];
    const float* bz  = (const float*)d_in[iBz];
    const float* lzw = (const float*)d_in[iLzw];
    const float* lzb = (const float*)d_in[iLzb];
    const float* Wr  = (const float*)d_in[iWr];
    const float* br  = (const float*)d_in[iBr];
    const float* lrw = (const float*)d_in[iLrw];
    const float* lrb = (const float*)d_in[iLrb];
    const float* Wh  = (const float*)d_in[iWh];
    const float* bh  = (const float*)d_in[iBh];
    const float* lhw = (const float*)d_in[iLhw];
    const float* lhb = (const float*)d_in[iLhb];
    const float* att  = (const float*)d_in[15];
    const float* linw = (const float*)d_in[16];
    const float* linb = (const float*)d_in[17];
    float* out = (float*)d_out;

    k_degcnt<<<(EE + 255) / 256, 256>>>(ei, ew);                      // 1
    k_scan_prep<<<1, 1024>>>(att, Wz, bz, lzw, lzb, Wr, br, lrw, lrb,
                             Wh, bh, lhw, lhb, linw);                 // 2
    k_fill<<<(EE + 255) / 256, 256>>>(ei, ew);                        // 3
    {   // 4: aggregation (ncu captures this one)
        int threads = NN * 6 * 32;
        k_agg<<<(threads + 255) / 256, 256>>>(x);
    }
    // 5: hybrid GRU — 626 scalar blocks (20032 rows) + 313 mma blocks
    //    (19968 rows + 1 skipped tail block), interleaved 2:1 per SM.
    k_ghyb<<<939, 128>>>(linw, linb, out);

    (void)n_in; (void)out_size;
}

// round 13
// speedup vs baseline: 1.1583x; 1.1583x over previous
#include <cuda_runtime.h>
#include <cuda_fp16.h>
#include <cstdint>

// Problem constants (fixed-shape problem)
#define BB 4
#define TT 12
#define NN 10000
#define FF 32
#define EE 160000
#define MM (BB*NN)          // 40000 rows
#define SLICES (BB*TT)      // 48
#define SL (NN*FF)          // 320000 elements per slice
#define SL2 (SL/2)          // slice stride in float2/ull units

typedef unsigned long long ull;

// -------- device scratch (static, no allocation; zero-initialized) --------
__device__ float d_XA[SLICES * NN * FF];   // aggregated features (61.4MB)
__device__ float d_deg[NN];
__device__ float d_dinv[NN];
__device__ int   d_cnt[NN];
__device__ int   d_fill[NN];
__device__ int   d_rowptr[NN + 1];
__device__ int2  d_csrp[EE];               // packed {src_row, weight_bits}
__device__ float d_bf[96];                 // folded biases z|r|h
__device__ float d_probs[TT];
// mma fragment-ordered f16x2 weights, 2-term (hi/lo): [term][nt][kt][lane][reg]
__device__ uint32_t d_fB1[2 * 12 * 4 * 32 * 2];   // gates B: K=64, N=96
__device__ uint32_t d_fUh[2 * 4 * 2 * 32 * 2];    // Uh:      K=32, N=32
__device__ uint32_t d_fLn[2 * 4 * 2 * 32 * 2];    // lin_w:   K=32, N=32

// ===================== f32x2 helpers (k_agg) =====================
__device__ __forceinline__ void fma2(ull& d, ull a, ull b) {
    asm("fma.rn.f32x2 %0, %1, %2, %0;" : "+l"(d) : "l"(a), "l"(b));
}
__device__ __forceinline__ void mul2(ull& d, ull a, ull b) {
    asm("mul.rn.f32x2 %0, %1, %2;" : "=l"(d) : "l"(a), "l"(b));
}
__device__ __forceinline__ ull splat2(float w) {
    ull r; asm("mov.b64 %0, {%1, %1};" : "=l"(r) : "f"(w)); return r;
}
__device__ __forceinline__ float2 unpk(ull a) {
    float2 f; asm("mov.b64 {%0, %1}, %2;" : "=f"(f.x), "=f"(f.y) : "l"(a)); return f;
}

// ===================== fp16 pack/split helpers =====================
__device__ __forceinline__ uint32_t packh(float a, float b) {
    __half2 h = __floats2half2_rn(a, b);        // x=a (low), y=b (high)
    return *(uint32_t*)&h;
}
// 2-term fp16 split of a pair
__device__ __forceinline__ void splith(float a, float b, uint32_t& hi, uint32_t& lo) {
    hi = packh(a, b);
    __half2 hh = *(__half2*)&hi;
    lo = packh(a - __half2float(hh.x), b - __half2float(hh.y));
}
// mma.sync m16n8k16 row.col fp16 -> f32, D += A*B
__device__ __forceinline__ void mma16816(float* d, const uint32_t* a,
                                         uint32_t b0, uint32_t b1) {
    asm("mma.sync.aligned.m16n8k16.row.col.f32.f16.f16.f32 "
        "{%0,%1,%2,%3}, {%4,%5,%6,%7}, {%8,%9}, {%0,%1,%2,%3};"
        : "+f"(d[0]), "+f"(d[1]), "+f"(d[2]), "+f"(d[3])
        : "r"(a[0]), "r"(a[1]), "r"(a[2]), "r"(a[3]), "r"(b0), "r"(b1));
}

// -------- degree/count accumulation --------
__global__ void k_degcnt(const int* ei, const float* ew) {
    int e = blockIdx.x * blockDim.x + threadIdx.x;
    if (e >= EE) return;
    int col = ei[EE + e];
    atomicAdd(&d_deg[col], ew[e]);
    atomicAdd(&d_cnt[col], 1);
}

// B1 element (k in [0,64), j in [0,96)): [W'z|W'r|W'h ; Uz|Ur|0]
__device__ __forceinline__ float b1elem(int k, int j,
        const float* Wz, const float* lzw, const float* Wr, const float* lrw,
        const float* Wh, const float* lhw) {
    int g = j >> 5, jj = j & 31;
    if (k < 32) {
        const float* Wg = (g == 0) ? Wz : (g == 1) ? Wr : Wh;
        const float* Lg = (g == 0) ? lzw : (g == 1) ? lrw : lhw;
        float s = 0.f;
        #pragma unroll
        for (int m = 0; m < 32; m++) s += Wg[k * 32 + m] * Lg[m * 32 + jj];
        return s;
    }
    return (g == 0) ? lzw[k * 32 + jj] : (g == 1) ? lrw[k * 32 + jj] : 0.f;
}

// single-block: dinv + scan + bias fold + softmax + fragment build + re-zero
__global__ void k_scan_prep(const float* att,
                            const float* Wz, const float* bz, const float* lzw, const float* lzb,
                            const float* Wr, const float* br, const float* lrw, const float* lrb,
                            const float* Wh, const float* bh, const float* lhw, const float* lhb,
                            const float* linw) {
    int tid = threadIdx.x;
    int lane = tid & 31;

    // ---- B1 fragments (fp16 hi/lo), fragment-native ordering ----
    for (int i = tid; i < 12 * 4 * 32; i += 1024) {
        int nt = i >> 7;
        int kt = (i >> 5) & 3;
        int ln = i & 31;
        int n = nt * 8 + (ln >> 2);
        int kb = kt * 16 + (ln & 3) * 2;
        #pragma unroll
        for (int r = 0; r < 2; r++) {
            int k0 = kb + r * 8;
            float w0 = b1elem(k0, n, Wz, lzw, Wr, lrw, Wh, lhw);
            float w1 = b1elem(k0 + 1, n, Wz, lzw, Wr, lrw, Wh, lhw);
            uint32_t hi, lo;
            splith(w0, w1, hi, lo);
            d_fB1[((0 * 12 + nt) * 4 + kt) * 64 + ln * 2 + r] = hi;
            d_fB1[((1 * 12 + nt) * 4 + kt) * 64 + ln * 2 + r] = lo;
        }
    }
    // ---- Uh + Ln fragments (K=32 -> kt in {0,1}, N=32 -> nt in {0..3}) ----
    for (int i = tid; i < 4 * 2 * 32; i += 1024) {
        int nt = i >> 6;
        int kt = (i >> 5) & 1;
        int ln = i & 31;
        int n = nt * 8 + (ln >> 2);
        int kb = kt * 16 + (ln & 3) * 2;
        #pragma unroll
        for (int r = 0; r < 2; r++) {
            int k0 = kb + r * 8;
            float u0 = lhw[(32 + k0) * 32 + n];
            float u1 = lhw[(32 + k0 + 1) * 32 + n];
            float l0 = linw[k0 * 32 + n];
            float l1 = linw[(k0 + 1) * 32 + n];
            uint32_t hi, lo;
            splith(u0, u1, hi, lo);
            d_fUh[((0 * 4 + nt) * 2 + kt) * 64 + ln * 2 + r] = hi;
            d_fUh[((1 * 4 + nt) * 2 + kt) * 64 + ln * 2 + r] = lo;
            splith(l0, l1, hi, lo);
            d_fLn[((0 * 4 + nt) * 2 + kt) * 64 + ln * 2 + r] = hi;
            d_fLn[((1 * 4 + nt) * 2 + kt) * 64 + ln * 2 + r] = lo;
        }
    }
    // ---- folded biases + softmax ----
    if (tid < 96) {
        int g = tid >> 5; int jj = tid & 31;
        const float* bs = (g == 0) ? bz : (g == 1) ? br : bh;
        const float* ls = (g == 0) ? lzw : (g == 1) ? lrw : lhw;
        const float* lb = (g == 0) ? lzb : (g == 1) ? lrb : lhb;
        float s = lb[jj];
        for (int m = 0; m < 32; m++) s += bs[m] * ls[m * 32 + jj];
        d_bf[g * 32 + jj] = s;
    }
    if (tid == 0) {
        float mx = -1e30f;
        for (int i = 0; i < TT; i++) mx = fmaxf(mx, att[i]);
        float e[TT]; float sum = 0.f;
        for (int i = 0; i < TT; i++) { e[i] = expf(att[i] - mx); sum += e[i]; }
        for (int i = 0; i < TT; i++) d_probs[i] = e[i] / sum;
    }

    // ---- dinv ----
    for (int i = tid; i < NN; i += 1024) {
        float d = d_deg[i] + 1.0f;
        d_dinv[i] = rsqrtf(fmaxf(d, 1e-12f));
    }
    // ---- 3-level exclusive scan ----
    __shared__ int warpsum[32];
    int v[10];
    int s = 0;
    int base = tid * 10;
    if (tid < 1000) {
        #pragma unroll
        for (int u = 0; u < 10; u++) { v[u] = s; s += d_cnt[base + u]; }
    }
    int inc = s;
    #pragma unroll
    for (int o = 1; o < 32; o <<= 1) {
        int t = __shfl_up_sync(0xffffffffu, inc, o);
        if (lane >= o) inc += t;
    }
    if (lane == 31) warpsum[tid >> 5] = inc;
    __syncthreads();
    if (tid < 32) {
        int ws = warpsum[tid];
        int winc = ws;
        #pragma unroll
        for (int o = 1; o < 32; o <<= 1) {
            int t = __shfl_up_sync(0xffffffffu, winc, o);
            if (lane >= o) winc += t;
        }
        warpsum[tid] = winc - ws;
    }
    __syncthreads();
    int texcl = warpsum[tid >> 5] + inc - s;
    if (tid < 1000) {
        #pragma unroll
        for (int u = 0; u < 10; u++) d_rowptr[base + u] = texcl + v[u];
    }
    if (tid == 1000) d_rowptr[NN] = texcl;

    __syncthreads();
    for (int i = tid; i < NN; i += 1024) { d_deg[i] = 0.f; d_cnt[i] = 0; d_fill[i] = 0; }
}

__global__ void k_fill(const int* ei, const float* ew) {
    int e = blockIdx.x * blockDim.x + threadIdx.x;
    if (e >= EE) return;
    int r = ei[e];
    int c = ei[EE + e];
    int pos = d_rowptr[c] + atomicAdd(&d_fill[c], 1);
    float w = d_dinv[r] * ew[e] * d_dinv[c];
    d_csrp[pos] = make_int2(r, __float_as_int(w));
}

// -------- aggregation (unchanged from baseline, at its L2 floor) --------
__global__ void __launch_bounds__(256) k_agg(const float* __restrict__ x) {
    int w = (blockIdx.x * blockDim.x + threadIdx.x) >> 5;
    int lane = threadIdx.x & 31;
    if (w >= NN * 6) return;
    int g = w / NN;
    int n = w - g * NN;
    int half = lane >> 4;
    int fp = lane & 15;

    const ull* px = (const ull*)x;
    int sbase = g * 8 + half;
    long ofs0 = (long)(sbase + 0) * SL2 + fp;
    long ofs1 = (long)(sbase + 2) * SL2 + fp;
    long ofs2 = (long)(sbase + 4) * SL2 + fp;
    long ofs3 = (long)(sbase + 6) * SL2 + fp;

    float dn = d_dinv[n];
    ull selfw2 = splat2(dn * dn);
    ull acc0, acc1, acc2, acc3;
    {
        int r16 = n * 16;
        mul2(acc0, __ldg(px + ofs0 + r16), selfw2);
        mul2(acc1, __ldg(px + ofs1 + r16), selfw2);
        mul2(acc2, __ldg(px + ofs2 + r16), selfw2);
        mul2(acc3, __ldg(px + ofs3 + r16), selfw2);
    }
    int e0 = d_rowptr[n], e1 = d_rowptr[n + 1];
    int2 ed;
    if (e0 < e1) ed = __ldg(&d_csrp[e0]);
    for (int e = e0; e < e1; e++) {
        int2 edn;
        if (e + 1 < e1) edn = __ldg(&d_csrp[e + 1]);
        ull w2 = splat2(__int_as_float(ed.y));
        int r16 = ed.x * 16;
        ull v0 = __ldg(px + ofs0 + r16);
        ull v1 = __ldg(px + ofs1 + r16);
        ull v2 = __ldg(px + ofs2 + r16);
        ull v3 = __ldg(px + ofs3 + r16);
        fma2(acc0, v0, w2);
        fma2(acc1, v1, w2);
        fma2(acc2, v2, w2);
        fma2(acc3, v3, w2);
        ed = edn;
    }
    float2* po = (float2*)d_XA;
    int n16 = n * 16 + fp;
    __stcs(po + (long)(sbase + 0) * SL2 + n16, unpk(acc0));
    __stcs(po + (long)(sbase + 2) * SL2 + n16, unpk(acc1));
    __stcs(po + (long)(sbase + 4) * SL2 + n16, unpk(acc2));
    __stcs(po + (long)(sbase + 6) * SL2 + n16, unpk(acc3));
}

// ==================== warp-MMA GRU (fp16, 1-term A x 2-term B) ====================
// Warp owns 16 rows; h/hacc live in registers for all 12 steps.
// Per step: z,r tiles (nt0-7): 4kt x 2 B-terms = 64 HMMA.
//           ah tiles (nt8-11): xa part kt0-1 x 2 = 16 (h columns of Wh are
//           exactly zero -> kt2-3 dropped), + hr@Uh 2kt x 2 = 16. Total 96.
__global__ void __launch_bounds__(128)
k_gruw(const float* __restrict__ linb, float* __restrict__ out) {
    __shared__ uint32_t sB1[6144];        // 24KB
    __shared__ uint32_t sUh[1024];        // 4KB
    __shared__ uint32_t sLn[1024];        // 4KB
    __shared__ float sbias[96];
    __shared__ float sprob[16];

    int tid = threadIdx.x;
    for (int i = tid; i < 6144; i += 128) sB1[i] = d_fB1[i];
    for (int i = tid; i < 1024; i += 128) { sUh[i] = d_fUh[i]; sLn[i] = d_fLn[i]; }
    if (tid < 96) sbias[tid] = d_bf[tid];
    if (tid < TT) sprob[tid] = d_probs[tid];
    __syncthreads();

    int lane = tid & 31;
    int wid = tid >> 5;
    int m0 = (blockIdx.x * 4 + wid) * 16;      // NN%16==0 -> no batch straddle
    int b = m0 / NN;
    long base = (long)b * (TT * SL) + (long)(m0 - b * NN) * 32;
    int r1 = lane >> 2;                        // fragment row (0..7)
    int c0 = (lane & 3) * 2;                   // fragment col base
    const float* xr1 = d_XA + base + (long)r1 * 32 + c0;        // row r1
    const float* xr2 = xr1 + 8 * 32;                            // row r1+8

    // h, hacc in D-fragment layout: [nt(0..3)][i(0..3)]
    float h[16], hacc[16];
    #pragma unroll
    for (int j = 0; j < 16; j++) { h[j] = 0.f; hacc[j] = 0.f; }

    for (int t = 0; t < TT; t++) {
        // ---- load xa (rows r1, r1+8; 4 col-pairs each) ----
        float2 x1[4], x2[4];
        #pragma unroll
        for (int q = 0; q < 4; q++) {
            x1[q] = __ldg((const float2*)(xr1 + (long)t * SL + 8 * q));
            x2[q] = __ldg((const float2*)(xr2 + (long)t * SL + 8 * q));
        }
        // ---- A fragments (1-term fp16): kt 0,1 from xa; kt 2,3 from h ----
        uint32_t a[4][4];
        #pragma unroll
        for (int kt = 0; kt < 2; kt++) {
            a[kt][0] = packh(x1[2 * kt].x,     x1[2 * kt].y);
            a[kt][1] = packh(x2[2 * kt].x,     x2[2 * kt].y);
            a[kt][2] = packh(x1[2 * kt + 1].x, x1[2 * kt + 1].y);
            a[kt][3] = packh(x2[2 * kt + 1].x, x2[2 * kt + 1].y);
        }
        #pragma unroll
        for (int kt = 2; kt < 4; kt++) {
            int hn = 2 * (kt - 2);
            a[kt][0] = packh(h[hn * 4 + 0],       h[hn * 4 + 1]);
            a[kt][1] = packh(h[hn * 4 + 2],       h[hn * 4 + 3]);
            a[kt][2] = packh(h[(hn + 1) * 4 + 0], h[(hn + 1) * 4 + 1]);
            a[kt][3] = packh(h[(hn + 1) * 4 + 2], h[(hn + 1) * 4 + 3]);
        }

        // ---- z, r gates: N-tiles 0..7 ----
        float z[16], hr[16];
        #pragma unroll
        for (int nt = 0; nt < 8; nt++) {
            float d[4];
            #pragma unroll
            for (int i = 0; i < 4; i++) d[i] = sbias[8 * nt + c0 + (i & 1)];
            #pragma unroll
            for (int kt = 0; kt < 4; kt++) {
                uint2 bh = *(const uint2*)&sB1[((0 * 12 + nt) * 4 + kt) * 64 + lane * 2];
                uint2 bl = *(const uint2*)&sB1[((1 * 12 + nt) * 4 + kt) * 64 + lane * 2];
                mma16816(d, a[kt], bh.x, bh.y);
                mma16816(d, a[kt], bl.x, bl.y);
            }
            if (nt < 4) {
                #pragma unroll
                for (int i = 0; i < 4; i++)
                    z[nt * 4 + i] = 1.f / (1.f + __expf(-d[i]));
            } else {
                int hn = nt - 4;
                #pragma unroll
                for (int i = 0; i < 4; i++) {
                    float rg = 1.f / (1.f + __expf(-d[i]));
                    hr[hn * 4 + i] = h[hn * 4 + i] * rg;
                }
            }
        }
        // ---- hr fragments (1-term fp16, K=32 -> kt 0,1) ----
        uint32_t rfr[2][4];
        #pragma unroll
        for (int kt = 0; kt < 2; kt++) {
            int hn = 2 * kt;
            rfr[kt][0] = packh(hr[hn * 4 + 0],       hr[hn * 4 + 1]);
            rfr[kt][1] = packh(hr[hn * 4 + 2],       hr[hn * 4 + 3]);
            rfr[kt][2] = packh(hr[(hn + 1) * 4 + 0], hr[(hn + 1) * 4 + 1]);
            rfr[kt][3] = packh(hr[(hn + 1) * 4 + 2], hr[(hn + 1) * 4 + 3]);
        }

        // ---- ah tiles: N-tiles 8..11; xa part (kt0,1 only) + hr@Uh ----
        float pt = sprob[t];
        #pragma unroll
        for (int nt = 8; nt < 12; nt++) {
            float d[4];
            #pragma unroll
            for (int i = 0; i < 4; i++) d[i] = sbias[8 * nt + c0 + (i & 1)];
            #pragma unroll
            for (int kt = 0; kt < 2; kt++) {      // kt 2,3 multiply zeros: dropped
                uint2 bh = *(const uint2*)&sB1[((0 * 12 + nt) * 4 + kt) * 64 + lane * 2];
                uint2 bl = *(const uint2*)&sB1[((1 * 12 + nt) * 4 + kt) * 64 + lane * 2];
                mma16816(d, a[kt], bh.x, bh.y);
                mma16816(d, a[kt], bl.x, bl.y);
            }
            int un = nt - 8;
            #pragma unroll
            for (int kt = 0; kt < 2; kt++) {
                uint2 bh = *(const uint2*)&sUh[((0 * 4 + un) * 2 + kt) * 64 + lane * 2];
                uint2 bl = *(const uint2*)&sUh[((1 * 4 + un) * 2 + kt) * 64 + lane * 2];
                mma16816(d, rfr[kt], bh.x, bh.y);
                mma16816(d, rfr[kt], bl.x, bl.y);
            }
            #pragma unroll
            for (int i = 0; i < 4; i++) {
                int j = un * 4 + i;
                float ht = 2.f / (1.f + __expf(-2.f * d[i])) - 1.f;   // tanh
                h[j] = z[j] * h[j] + (1.f - z[j]) * ht;
                hacc[j] += pt * h[j];
            }
        }
    }

    // ---- final: out = relu(hacc) @ lin_w + lin_b ----
    uint32_t rfr[2][4];
    #pragma unroll
    for (int kt = 0; kt < 2; kt++) {
        int hn = 2 * kt;
        rfr[kt][0] = packh(fmaxf(hacc[hn * 4 + 0], 0.f),       fmaxf(hacc[hn * 4 + 1], 0.f));
        rfr[kt][1] = packh(fmaxf(hacc[hn * 4 + 2], 0.f),       fmaxf(hacc[hn * 4 + 3], 0.f));
        rfr[kt][2] = packh(fmaxf(hacc[(hn + 1) * 4 + 0], 0.f), fmaxf(hacc[(hn + 1) * 4 + 1], 0.f));
        rfr[kt][3] = packh(fmaxf(hacc[(hn + 1) * 4 + 2], 0.f), fmaxf(hacc[(hn + 1) * 4 + 3], 0.f));
    }
    #pragma unroll
    for (int nt = 0; nt < 4; nt++) {
        float d[4];
        float lb0 = __ldg(&linb[8 * nt + c0]);
        float lb1 = __ldg(&linb[8 * nt + c0 + 1]);
        d[0] = lb0; d[1] = lb1; d[2] = lb0; d[3] = lb1;
        #pragma unroll
        for (int kt = 0; kt < 2; kt++) {
            uint2 bh = *(const uint2*)&sLn[((0 * 4 + nt) * 2 + kt) * 64 + lane * 2];
            uint2 bl = *(const uint2*)&sLn[((1 * 4 + nt) * 2 + kt) * 64 + lane * 2];
            mma16816(d, rfr[kt], bh.x, bh.y);
            mma16816(d, rfr[kt], bl.x, bl.y);
        }
        *(float2*)(out + (long)(m0 + r1) * 32 + 8 * nt + c0)     = make_float2(d[0], d[1]);
        *(float2*)(out + (long)(m0 + r1 + 8) * 32 + 8 * nt + c0) = make_float2(d[2], d[3]);
    }
}

extern "C" void kernel_launch(void* const* d_in, const int* in_sizes, int n_in,
                              void* d_out, int out_size) {
    const float* x  = (const float*)d_in[0];
    const int*   ei = (const int*)d_in[1];
    const float* ew = (const float*)d_in[2];

    int iWz, iBz, iLzw, iLzb, iWr, iBr, iLrw, iLrb, iWh, iBh, iLhw, iLhb;
    if (in_sizes[5] == 2048) {
        iWz = 3; iBz = 4; iLzw = 5;  iLzb = 6;
        iWr = 7; iBr = 8; iLrw = 9;  iLrb = 10;
        iWh = 11; iBh = 12; iLhw = 13; iLhb = 14;
    } else {
        iWz = 3; iBz = 4; iWr = 5; iBr = 6; iWh = 7; iBh = 8;
        iLzw = 9; iLzb = 10; iLrw = 11; iLrb = 12; iLhw = 13; iLhb = 14;
    }
    const float* Wz  = (const float*)d_in[iWz];
    const float* bz  = (const float*)d_in[iBz];
    const float* lzw = (const float*)d_in[iLzw];
    const float* lzb = (const float*)d_in[iLzb];
    const float* Wr  = (const float*)d_in[iWr];
    const float* br  = (const float*)d_in[iBr];
    const float* lrw = (const float*)d_in[iLrw];
    const float* lrb = (const float*)d_in[iLrb];
    const float* Wh  = (const float*)d_in[iWh];
    const float* bh  = (const float*)d_in[iBh];
    const float* lhw = (const float*)d_in[iLhw];
    const float* lhb = (const float*)d_in[iLhb];
    const float* att  = (const float*)d_in[15];
    const float* linw = (const float*)d_in[16];
    const float* linb = (const float*)d_in[17];
    float* out = (float*)d_out;

    k_degcnt<<<(EE + 255) / 256, 256>>>(ei, ew);                      // 1
    k_scan_prep<<<1, 1024>>>(att, Wz, bz, lzw, lzb, Wr, br, lrw, lrb,
                             Wh, bh, lhw, lhb, linw);                 // 2
    k_fill<<<(EE + 255) / 256, 256>>>(ei, ew);                        // 3
    {   // 4: aggregation (ncu captures this one)
        int threads = NN * 6 * 32;
        k_agg<<<(threads + 255) / 256, 256>>>(x);
    }
    k_gruw<<<MM / 64, 128>>>(linb, out);                              // 5

    (void)n_in; (void)out_size;
}

// round 14
// speedup vs baseline: 1.2288x; 1.0609x over previous
#include <cuda_runtime.h>
#include <cuda_fp16.h>
#include <cstdint>

// Problem constants (fixed-shape problem)
#define BB 4
#define TT 12
#define NN 10000
#define FF 32
#define EE 160000
#define MM (BB*NN)          // 40000 rows
#define SLICES (BB*TT)      // 48
#define SL (NN*FF)          // 320000 elements per slice
#define SL2 (SL/2)          // slice stride in float2 / fp16x2-pair units

typedef unsigned long long ull;

// -------- device scratch (static, no allocation; zero-initialized) --------
__device__ uint32_t d_XAh[SLICES * NN * 16];  // aggregated features, fp16x2-packed (30.7MB)
__device__ float d_deg[NN];
__device__ float d_dinv[NN];
__device__ int   d_cnt[NN];
__device__ int   d_fill[NN];
__device__ int   d_rowptr[NN + 1];
__device__ int2  d_csrp[EE];               // packed {src_row, weight_bits}
__device__ float d_bf[96];                 // folded biases z|r|h
__device__ float d_probs[TT];
// mma fragment-ordered f16x2 weights, 2-term (hi/lo): [term][nt][kt][lane][reg]
__device__ uint32_t d_fB1[2 * 12 * 4 * 32 * 2];   // gates B: K=64, N=96
__device__ uint32_t d_fUh[2 * 4 * 2 * 32 * 2];    // Uh:      K=32, N=32
__device__ uint32_t d_fLn[2 * 4 * 2 * 32 * 2];    // lin_w:   K=32, N=32

// ===================== f32x2 helpers (k_agg) =====================
__device__ __forceinline__ void fma2(ull& d, ull a, ull b) {
    asm("fma.rn.f32x2 %0, %1, %2, %0;" : "+l"(d) : "l"(a), "l"(b));
}
__device__ __forceinline__ void mul2(ull& d, ull a, ull b) {
    asm("mul.rn.f32x2 %0, %1, %2;" : "=l"(d) : "l"(a), "l"(b));
}
__device__ __forceinline__ ull splat2(float w) {
    ull r; asm("mov.b64 %0, {%1, %1};" : "=l"(r) : "f"(w)); return r;
}
__device__ __forceinline__ float2 unpk(ull a) {
    float2 f; asm("mov.b64 {%0, %1}, %2;" : "=f"(f.x), "=f"(f.y) : "l"(a)); return f;
}

// ===================== fp16 pack/split helpers =====================
__device__ __forceinline__ uint32_t packh(float a, float b) {
    __half2 h = __floats2half2_rn(a, b);        // x=a (low), y=b (high)
    return *(uint32_t*)&h;
}
// 2-term fp16 split of a pair
__device__ __forceinline__ void splith(float a, float b, uint32_t& hi, uint32_t& lo) {
    hi = packh(a, b);
    __half2 hh = *(__half2*)&hi;
    lo = packh(a - __half2float(hh.x), b - __half2float(hh.y));
}
// mma.sync m16n8k16 row.col fp16 -> f32, D += A*B
__device__ __forceinline__ void mma16816(float* d, const uint32_t* a,
                                         uint32_t b0, uint32_t b1) {
    asm("mma.sync.aligned.m16n8k16.row.col.f32.f16.f16.f32 "
        "{%0,%1,%2,%3}, {%4,%5,%6,%7}, {%8,%9}, {%0,%1,%2,%3};"
        : "+f"(d[0]), "+f"(d[1]), "+f"(d[2]), "+f"(d[3])
        : "r"(a[0]), "r"(a[1]), "r"(a[2]), "r"(a[3]), "r"(b0), "r"(b1));
}

// -------- degree/count accumulation --------
__global__ void k_degcnt(const int* ei, const float* ew) {
    int e = blockIdx.x * blockDim.x + threadIdx.x;
    if (e >= EE) return;
    int col = ei[EE + e];
    atomicAdd(&d_deg[col], ew[e]);
    atomicAdd(&d_cnt[col], 1);
}

// B1 element (k in [0,64), j in [0,96)): [W'z|W'r|W'h ; Uz|Ur|0]
__device__ __forceinline__ float b1elem(int k, int j,
        const float* Wz, const float* lzw, const float* Wr, const float* lrw,
        const float* Wh, const float* lhw) {
    int g = j >> 5, jj = j & 31;
    if (k < 32) {
        const float* Wg = (g == 0) ? Wz : (g == 1) ? Wr : Wh;
        const float* Lg = (g == 0) ? lzw : (g == 1) ? lrw : lhw;
        float s = 0.f;
        #pragma unroll
        for (int m = 0; m < 32; m++) s += Wg[k * 32 + m] * Lg[m * 32 + jj];
        return s;
    }
    return (g == 0) ? lzw[k * 32 + jj] : (g == 1) ? lrw[k * 32 + jj] : 0.f;
}

// single-block: dinv + scan + bias fold + softmax + fragment build + re-zero
__global__ void k_scan_prep(const float* att,
                            const float* Wz, const float* bz, const float* lzw, const float* lzb,
                            const float* Wr, const float* br, const float* lrw, const float* lrb,
                            const float* Wh, const float* bh, const float* lhw, const float* lhb,
                            const float* linw) {
    int tid = threadIdx.x;
    int lane = tid & 31;

    // ---- B1 fragments (fp16 hi/lo), fragment-native ordering ----
    for (int i = tid; i < 12 * 4 * 32; i += 1024) {
        int nt = i >> 7;
        int kt = (i >> 5) & 3;
        int ln = i & 31;
        int n = nt * 8 + (ln >> 2);
        int kb = kt * 16 + (ln & 3) * 2;
        #pragma unroll
        for (int r = 0; r < 2; r++) {
            int k0 = kb + r * 8;
            float w0 = b1elem(k0, n, Wz, lzw, Wr, lrw, Wh, lhw);
            float w1 = b1elem(k0 + 1, n, Wz, lzw, Wr, lrw, Wh, lhw);
            uint32_t hi, lo;
            splith(w0, w1, hi, lo);
            d_fB1[((0 * 12 + nt) * 4 + kt) * 64 + ln * 2 + r] = hi;
            d_fB1[((1 * 12 + nt) * 4 + kt) * 64 + ln * 2 + r] = lo;
        }
    }
    // ---- Uh + Ln fragments (K=32 -> kt in {0,1}, N=32 -> nt in {0..3}) ----
    for (int i = tid; i < 4 * 2 * 32; i += 1024) {
        int nt = i >> 6;
        int kt = (i >> 5) & 1;
        int ln = i & 31;
        int n = nt * 8 + (ln >> 2);
        int kb = kt * 16 + (ln & 3) * 2;
        #pragma unroll
        for (int r = 0; r < 2; r++) {
            int k0 = kb + r * 8;
            float u0 = lhw[(32 + k0) * 32 + n];
            float u1 = lhw[(32 + k0 + 1) * 32 + n];
            float l0 = linw[k0 * 32 + n];
            float l1 = linw[(k0 + 1) * 32 + n];
            uint32_t hi, lo;
            splith(u0, u1, hi, lo);
            d_fUh[((0 * 4 + nt) * 2 + kt) * 64 + ln * 2 + r] = hi;
            d_fUh[((1 * 4 + nt) * 2 + kt) * 64 + ln * 2 + r] = lo;
            splith(l0, l1, hi, lo);
            d_fLn[((0 * 4 + nt) * 2 + kt) * 64 + ln * 2 + r] = hi;
            d_fLn[((1 * 4 + nt) * 2 + kt) * 64 + ln * 2 + r] = lo;
        }
    }
    // ---- folded biases + softmax ----
    if (tid < 96) {
        int g = tid >> 5; int jj = tid & 31;
        const float* bs = (g == 0) ? bz : (g == 1) ? br : bh;
        const float* ls = (g == 0) ? lzw : (g == 1) ? lrw : lhw;
        const float* lb = (g == 0) ? lzb : (g == 1) ? lrb : lhb;
        float s = lb[jj];
        for (int m = 0; m < 32; m++) s += bs[m] * ls[m * 32 + jj];
        d_bf[g * 32 + jj] = s;
    }
    if (tid == 0) {
        float mx = -1e30f;
        for (int i = 0; i < TT; i++) mx = fmaxf(mx, att[i]);
        float e[TT]; float sum = 0.f;
        for (int i = 0; i < TT; i++) { e[i] = expf(att[i] - mx); sum += e[i]; }
        for (int i = 0; i < TT; i++) d_probs[i] = e[i] / sum;
    }

    // ---- dinv ----
    for (int i = tid; i < NN; i += 1024) {
        float d = d_deg[i] + 1.0f;
        d_dinv[i] = rsqrtf(fmaxf(d, 1e-12f));
    }
    // ---- 3-level exclusive scan ----
    __shared__ int warpsum[32];
    int v[10];
    int s = 0;
    int base = tid * 10;
    if (tid < 1000) {
        #pragma unroll
        for (int u = 0; u < 10; u++) { v[u] = s; s += d_cnt[base + u]; }
    }
    int inc = s;
    #pragma unroll
    for (int o = 1; o < 32; o <<= 1) {
        int t = __shfl_up_sync(0xffffffffu, inc, o);
        if (lane >= o) inc += t;
    }
    if (lane == 31) warpsum[tid >> 5] = inc;
    __syncthreads();
    if (tid < 32) {
        int ws = warpsum[tid];
        int winc = ws;
        #pragma unroll
        for (int o = 1; o < 32; o <<= 1) {
            int t = __shfl_up_sync(0xffffffffu, winc, o);
            if (lane >= o) winc += t;
        }
        warpsum[tid] = winc - ws;
    }
    __syncthreads();
    int texcl = warpsum[tid >> 5] + inc - s;
    if (tid < 1000) {
        #pragma unroll
        for (int u = 0; u < 10; u++) d_rowptr[base + u] = texcl + v[u];
    }
    if (tid == 1000) d_rowptr[NN] = texcl;

    __syncthreads();
    for (int i = tid; i < NN; i += 1024) { d_deg[i] = 0.f; d_cnt[i] = 0; d_fill[i] = 0; }
}

__global__ void k_fill(const int* ei, const float* ew) {
    int e = blockIdx.x * blockDim.x + threadIdx.x;
    if (e >= EE) return;
    int r = ei[e];
    int c = ei[EE + e];
    int pos = d_rowptr[c] + atomicAdd(&d_fill[c], 1);
    float w = d_dinv[r] * ew[e] * d_dinv[c];
    d_csrp[pos] = make_int2(r, __float_as_int(w));
}

// -------- aggregation: gather in f32, store XA as fp16x2 (pair-packed) ----
// Storing fp16 is precision-free relative to R13: gru rounded xa to fp16 in
// its A-fragment pack anyway; the rounding just moved into this store.
__global__ void __launch_bounds__(256) k_agg(const float* __restrict__ x) {
    int w = (blockIdx.x * blockDim.x + threadIdx.x) >> 5;
    int lane = threadIdx.x & 31;
    if (w >= NN * 6) return;
    int g = w / NN;
    int n = w - g * NN;
    int half = lane >> 4;
    int fp = lane & 15;

    const ull* px = (const ull*)x;
    int sbase = g * 8 + half;
    long ofs0 = (long)(sbase + 0) * SL2 + fp;
    long ofs1 = (long)(sbase + 2) * SL2 + fp;
    long ofs2 = (long)(sbase + 4) * SL2 + fp;
    long ofs3 = (long)(sbase + 6) * SL2 + fp;

    float dn = d_dinv[n];
    ull selfw2 = splat2(dn * dn);
    ull acc0, acc1, acc2, acc3;
    {
        int r16 = n * 16;
        mul2(acc0, __ldg(px + ofs0 + r16), selfw2);
        mul2(acc1, __ldg(px + ofs1 + r16), selfw2);
        mul2(acc2, __ldg(px + ofs2 + r16), selfw2);
        mul2(acc3, __ldg(px + ofs3 + r16), selfw2);
    }
    int e0 = d_rowptr[n], e1 = d_rowptr[n + 1];
    int2 ed;
    if (e0 < e1) ed = __ldg(&d_csrp[e0]);
    for (int e = e0; e < e1; e++) {
        int2 edn;
        if (e + 1 < e1) edn = __ldg(&d_csrp[e + 1]);
        ull w2 = splat2(__int_as_float(ed.y));
        int r16 = ed.x * 16;
        ull v0 = __ldg(px + ofs0 + r16);
        ull v1 = __ldg(px + ofs1 + r16);
        ull v2 = __ldg(px + ofs2 + r16);
        ull v3 = __ldg(px + ofs3 + r16);
        fma2(acc0, v0, w2);
        fma2(acc1, v1, w2);
        fma2(acc2, v2, w2);
        fma2(acc3, v3, w2);
        ed = edn;
    }
    int n16 = n * 16 + fp;
    float2 f0 = unpk(acc0), f1 = unpk(acc1), f2 = unpk(acc2), f3 = unpk(acc3);
    __stcs(&d_XAh[(long)(sbase + 0) * SL2 + n16], packh(f0.x, f0.y));
    __stcs(&d_XAh[(long)(sbase + 2) * SL2 + n16], packh(f1.x, f1.y));
    __stcs(&d_XAh[(long)(sbase + 4) * SL2 + n16], packh(f2.x, f2.y));
    __stcs(&d_XAh[(long)(sbase + 6) * SL2 + n16], packh(f3.x, f3.y));
}

// ==================== warp-MMA GRU (fp16) ====================
// Warp owns 16 rows; h/hacc in registers for all 12 steps.
// HMMA per warp-step: z/r tiles (nt0-7) 1-term B = 32 (gate noise is
// sigmoid-damped); ah tiles (nt8-11) 2-term B: xa 16 + Uh 16. Total 64.
// xa A-fragments load pre-packed fp16x2 straight from d_XAh.
__global__ void __launch_bounds__(128)
k_gruw(const float* __restrict__ linb, float* __restrict__ out) {
    __shared__ uint32_t sB1[6144];        // 24KB
    __shared__ uint32_t sUh[1024];        // 4KB
    __shared__ uint32_t sLn[1024];        // 4KB
    __shared__ float sbias[96];
    __shared__ float sprob[16];

    int tid = threadIdx.x;
    for (int i = tid; i < 6144; i += 128) sB1[i] = d_fB1[i];
    for (int i = tid; i < 1024; i += 128) { sUh[i] = d_fUh[i]; sLn[i] = d_fLn[i]; }
    if (tid < 96) sbias[tid] = d_bf[tid];
    if (tid < TT) sprob[tid] = d_probs[tid];
    __syncthreads();

    int lane = tid & 31;
    int wid = tid >> 5;
    int m0 = (blockIdx.x * 4 + wid) * 16;      // NN%16==0 -> no batch straddle
    int b = m0 / NN;
    long basep = (long)b * (TT * SL2) + (long)(m0 - b * NN) * 16;   // pair units
    int r1 = lane >> 2;                        // fragment row (0..7)
    int c0q = lane & 3;                        // fragment col-pair index
    const uint32_t* xr1 = d_XAh + basep + (long)r1 * 16 + c0q;      // row r1
    const uint32_t* xr2 = xr1 + 8 * 16;                             // row r1+8
    int c0 = c0q * 2;

    // h, hacc in D-fragment layout: [nt(0..3)][i(0..3)]
    float h[16], hacc[16];
    #pragma unroll
    for (int j = 0; j < 16; j++) { h[j] = 0.f; hacc[j] = 0.f; }

    for (int t = 0; t < TT; t++) {
        // ---- A fragments: kt 0,1 pre-packed from XAh; kt 2,3 from h ----
        uint32_t a[4][4];
        #pragma unroll
        for (int kt = 0; kt < 2; kt++) {
            a[kt][0] = __ldg(xr1 + (long)t * SL2 + 4 * (2 * kt));
            a[kt][1] = __ldg(xr2 + (long)t * SL2 + 4 * (2 * kt));
            a[kt][2] = __ldg(xr1 + (long)t * SL2 + 4 * (2 * kt + 1));
            a[kt][3] = __ldg(xr2 + (long)t * SL2 + 4 * (2 * kt + 1));
        }
        #pragma unroll
        for (int kt = 2; kt < 4; kt++) {
            int hn = 2 * (kt - 2);
            a[kt][0] = packh(h[hn * 4 + 0],       h[hn * 4 + 1]);
            a[kt][1] = packh(h[hn * 4 + 2],       h[hn * 4 + 3]);
            a[kt][2] = packh(h[(hn + 1) * 4 + 0], h[(hn + 1) * 4 + 1]);
            a[kt][3] = packh(h[(hn + 1) * 4 + 2], h[(hn + 1) * 4 + 3]);
        }

        // ---- z, r gates: N-tiles 0..7, 1-term B ----
        float z[16], hr[16];
        #pragma unroll
        for (int nt = 0; nt < 8; nt++) {
            float d[4];
            #pragma unroll
            for (int i = 0; i < 4; i++) d[i] = sbias[8 * nt + c0 + (i & 1)];
            #pragma unroll
            for (int kt = 0; kt < 4; kt++) {
                uint2 bh = *(const uint2*)&sB1[((0 * 12 + nt) * 4 + kt) * 64 + lane * 2];
                mma16816(d, a[kt], bh.x, bh.y);
            }
            if (nt < 4) {
                #pragma unroll
                for (int i = 0; i < 4; i++)
                    z[nt * 4 + i] = 1.f / (1.f + __expf(-d[i]));
            } else {
                int hn = nt - 4;
                #pragma unroll
                for (int i = 0; i < 4; i++) {
                    float rg = 1.f / (1.f + __expf(-d[i]));
                    hr[hn * 4 + i] = h[hn * 4 + i] * rg;
                }
            }
        }
        // ---- hr fragments (1-term fp16, K=32 -> kt 0,1) ----
        uint32_t rfr[2][4];
        #pragma unroll
        for (int kt = 0; kt < 2; kt++) {
            int hn = 2 * kt;
            rfr[kt][0] = packh(hr[hn * 4 + 0],       hr[hn * 4 + 1]);
            rfr[kt][1] = packh(hr[hn * 4 + 2],       hr[hn * 4 + 3]);
            rfr[kt][2] = packh(hr[(hn + 1) * 4 + 0], hr[(hn + 1) * 4 + 1]);
            rfr[kt][3] = packh(hr[(hn + 1) * 4 + 2], hr[(hn + 1) * 4 + 3]);
        }

        // ---- ah tiles: N-tiles 8..11; xa part (kt0,1) + hr@Uh, 2-term B ----
        float pt = sprob[t];
        #pragma unroll
        for (int nt = 8; nt < 12; nt++) {
            float d[4];
            #pragma unroll
            for (int i = 0; i < 4; i++) d[i] = sbias[8 * nt + c0 + (i & 1)];
            #pragma unroll
            for (int kt = 0; kt < 2; kt++) {      // kt 2,3 multiply zeros: dropped
                uint2 bh = *(const uint2*)&sB1[((0 * 12 + nt) * 4 + kt) * 64 + lane * 2];
                uint2 bl = *(const uint2*)&sB1[((1 * 12 + nt) * 4 + kt) * 64 + lane * 2];
                mma16816(d, a[kt], bh.x, bh.y);
                mma16816(d, a[kt], bl.x, bl.y);
            }
            int un = nt - 8;
            #pragma unroll
            for (int kt = 0; kt < 2; kt++) {
                uint2 bh = *(const uint2*)&sUh[((0 * 4 + un) * 2 + kt) * 64 + lane * 2];
                uint2 bl = *(const uint2*)&sUh[((1 * 4 + un) * 2 + kt) * 64 + lane * 2];
                mma16816(d, rfr[kt], bh.x, bh.y);
                mma16816(d, rfr[kt], bl.x, bl.y);
            }
            #pragma unroll
            for (int i = 0; i < 4; i++) {
                int j = un * 4 + i;
                float ht = 2.f / (1.f + __expf(-2.f * d[i])) - 1.f;   // tanh
                h[j] = z[j] * h[j] + (1.f - z[j]) * ht;
                hacc[j] += pt * h[j];
            }
        }
    }

    // ---- final: out = relu(hacc) @ lin_w + lin_b (2-term B) ----
    uint32_t rfr[2][4];
    #pragma unroll
    for (int kt = 0; kt < 2; kt++) {
        int hn = 2 * kt;
        rfr[kt][0] = packh(fmaxf(hacc[hn * 4 + 0], 0.f),       fmaxf(hacc[hn * 4 + 1], 0.f));
        rfr[kt][1] = packh(fmaxf(hacc[hn * 4 + 2], 0.f),       fmaxf(hacc[hn * 4 + 3], 0.f));
        rfr[kt][2] = packh(fmaxf(hacc[(hn + 1) * 4 + 0], 0.f), fmaxf(hacc[(hn + 1) * 4 + 1], 0.f));
        rfr[kt][3] = packh(fmaxf(hacc[(hn + 1) * 4 + 2], 0.f), fmaxf(hacc[(hn + 1) * 4 + 3], 0.f));
    }
    #pragma unroll
    for (int nt = 0; nt < 4; nt++) {
        float d[4];
        float lb0 = __ldg(&linb[8 * nt + c0]);
        float lb1 = __ldg(&linb[8 * nt + c0 + 1]);
        d[0] = lb0; d[1] = lb1; d[2] = lb0; d[3] = lb1;
        #pragma unroll
        for (int kt = 0; kt < 2; kt++) {
            uint2 bh = *(const uint2*)&sLn[((0 * 4 + nt) * 2 + kt) * 64 + lane * 2];
            uint2 bl = *(const uint2*)&sLn[((1 * 4 + nt) * 2 + kt) * 64 + lane * 2];
            mma16816(d, rfr[kt], bh.x, bh.y);
            mma16816(d, rfr[kt], bl.x, bl.y);
        }
        *(float2*)(out + (long)(m0 + r1) * 32 + 8 * nt + c0)     = make_float2(d[0], d[1]);
        *(float2*)(out + (long)(m0 + r1 + 8) * 32 + 8 * nt + c0) = make_float2(d[2], d[3]);
    }
}

extern "C" void kernel_launch(void* const* d_in, const int* in_sizes, int n_in,
                              void* d_out, int out_size) {
    const float* x  = (const float*)d_in[0];
    const int*   ei = (const int*)d_in[1];
    const float* ew = (const float*)d_in[2];

    int iWz, iBz, iLzw, iLzb, iWr, iBr, iLrw, iLrb, iWh, iBh, iLhw, iLhb;
    if (in_sizes[5] == 2048) {
        iWz = 3; iBz = 4; iLzw = 5;  iLzb = 6;
        iWr = 7; iBr = 8; iLrw = 9;  iLrb = 10;
        iWh = 11; iBh = 12; iLhw = 13; iLhb = 14;
    } else {
        iWz = 3; iBz = 4; iWr = 5; iBr = 6; iWh = 7; iBh = 8;
        iLzw = 9; iLzb = 10; iLrw = 11; iLrb = 12; iLhw = 13; iLhb = 14;
    }
    const float* Wz  = (const float*)d_in[iWz];
    const float* bz  = (const float*)d_in[iBz];
    const float* lzw = (const float*)d_in[iLzw];
    const float* lzb = (const float*)d_in[iLzb];
    const float* Wr  = (const float*)d_in[iWr];
    const float* br  = (const float*)d_in[iBr];
    const float* lrw = (const float*)d_in[iLrw];
    const float* lrb = (const float*)d_in[iLrb];
    const float* Wh  = (const float*)d_in[iWh];
    const float* bh  = (const float*)d_in[iBh];
    const float* lhw = (const float*)d_in[iLhw];
    const float* lhb = (const float*)d_in[iLhb];
    const float* att  = (const float*)d_in[15];
    const float* linw = (const float*)d_in[16];
    const float* linb = (const float*)d_in[17];
    float* out = (float*)d_out;

    k_degcnt<<<(EE + 255) / 256, 256>>>(ei, ew);                      // 1
    k_scan_prep<<<1, 1024>>>(att, Wz, bz, lzw, lzb, Wr, br, lrw, lrb,
                             Wh, bh, lhw, lhb, linw);                 // 2
    k_fill<<<(EE + 255) / 256, 256>>>(ei, ew);                        // 3
    {   // 4: aggregation (ncu captures this one)
        int threads = NN * 6 * 32;
        k_agg<<<(threads + 255) / 256, 256>>>(x);
    }
    k_gruw<<<MM / 64, 128>>>(linb, out);                              // 5

    (void)n_in; (void)out_size;
}

// round 15
// speedup vs baseline: 1.2612x; 1.0264x over previous
#include <cuda_runtime.h>
#include <cuda_fp16.h>
#include <cstdint>

// Problem constants (fixed-shape problem)
#define BB 4
#define TT 12
#define NN 10000
#define FF 32
#define EE 160000
#define MM (BB*NN)          // 40000 rows
#define SLICES (BB*TT)      // 48
#define SL (NN*FF)          // 320000 elements per slice
#define SL2 (SL/2)          // slice stride in float2 / fp16x2-pair units
#define NTASK (MM/16)       // 2500 gru row-groups

typedef unsigned long long ull;

// -------- device scratch (static, no allocation; zero-initialized) --------
__device__ uint32_t d_XAh[SLICES * NN * 16];  // aggregated features, fp16x2 (30.7MB)
__device__ float d_deg[NN];
__device__ float d_dinv[NN];
__device__ int   d_cnt[NN];
__device__ int   d_fill[NN];
__device__ int   d_rowptr[NN + 1];
__device__ int2  d_csrp[EE];               // packed {src_row, weight_bits}
__device__ float d_bf[96];                 // folded biases z|r|h
__device__ float d_probs[TT];
// mma fragment-ordered f16x2 weights, 2-term (hi/lo): [term][nt][kt][lane][reg]
__device__ uint32_t d_fB1[2 * 12 * 4 * 32 * 2];   // gates B: K=64, N=96
__device__ uint32_t d_fUh[2 * 4 * 2 * 32 * 2];    // Uh:      K=32, N=32
__device__ uint32_t d_fLn[2 * 4 * 2 * 32 * 2];    // lin_w:   K=32, N=32

// ===================== f32x2 helpers (k_agg) =====================
__device__ __forceinline__ void fma2(ull& d, ull a, ull b) {
    asm("fma.rn.f32x2 %0, %1, %2, %0;" : "+l"(d) : "l"(a), "l"(b));
}
__device__ __forceinline__ void mul2(ull& d, ull a, ull b) {
    asm("mul.rn.f32x2 %0, %1, %2;" : "=l"(d) : "l"(a), "l"(b));
}
__device__ __forceinline__ ull splat2(float w) {
    ull r; asm("mov.b64 %0, {%1, %1};" : "=l"(r) : "f"(w)); return r;
}
__device__ __forceinline__ float2 unpk(ull a) {
    float2 f; asm("mov.b64 {%0, %1}, %2;" : "=f"(f.x), "=f"(f.y) : "l"(a)); return f;
}

// ===================== fp16 pack/split helpers =====================
__device__ __forceinline__ uint32_t packh(float a, float b) {
    __half2 h = __floats2half2_rn(a, b);        // x=a (low), y=b (high)
    return *(uint32_t*)&h;
}
// 2-term fp16 split of a pair
__device__ __forceinline__ void splith(float a, float b, uint32_t& hi, uint32_t& lo) {
    hi = packh(a, b);
    __half2 hh = *(__half2*)&hi;
    lo = packh(a - __half2float(hh.x), b - __half2float(hh.y));
}
// mma.sync m16n8k16 row.col fp16 -> f32, D += A*B
__device__ __forceinline__ void mma16816(float* d, const uint32_t* a,
                                         uint32_t b0, uint32_t b1) {
    asm("mma.sync.aligned.m16n8k16.row.col.f32.f16.f16.f32 "
        "{%0,%1,%2,%3}, {%4,%5,%6,%7}, {%8,%9}, {%0,%1,%2,%3};"
        : "+f"(d[0]), "+f"(d[1]), "+f"(d[2]), "+f"(d[3])
        : "r"(a[0]), "r"(a[1]), "r"(a[2]), "r"(a[3]), "r"(b0), "r"(b1));
}

// -------- degree/count accumulation --------
__global__ void k_degcnt(const int* ei, const float* ew) {
    int e = blockIdx.x * blockDim.x + threadIdx.x;
    if (e >= EE) return;
    int col = ei[EE + e];
    atomicAdd(&d_deg[col], ew[e]);
    atomicAdd(&d_cnt[col], 1);
}

// B1 element (k in [0,64), j in [0,96)): [W'z|W'r|W'h ; Uz|Ur|0]
__device__ __forceinline__ float b1elem(int k, int j,
        const float* Wz, const float* lzw, const float* Wr, const float* lrw,
        const float* Wh, const float* lhw) {
    int g = j >> 5, jj = j & 31;
    if (k < 32) {
        const float* Wg = (g == 0) ? Wz : (g == 1) ? Wr : Wh;
        const float* Lg = (g == 0) ? lzw : (g == 1) ? lrw : lhw;
        float s = 0.f;
        #pragma unroll
        for (int m = 0; m < 32; m++) s += Wg[k * 32 + m] * Lg[m * 32 + jj];
        return s;
    }
    return (g == 0) ? lzw[k * 32 + jj] : (g == 1) ? lrw[k * 32 + jj] : 0.f;
}

// single-block: dinv + scan + bias fold + softmax + fragment build + re-zero
__global__ void k_scan_prep(const float* att,
                            const float* Wz, const float* bz, const float* lzw, const float* lzb,
                            const float* Wr, const float* br, const float* lrw, const float* lrb,
                            const float* Wh, const float* bh, const float* lhw, const float* lhb,
                            const float* linw) {
    int tid = threadIdx.x;
    int lane = tid & 31;

    // ---- B1 fragments (fp16 hi/lo), fragment-native ordering ----
    for (int i = tid; i < 12 * 4 * 32; i += 1024) {
        int nt = i >> 7;
        int kt = (i >> 5) & 3;
        int ln = i & 31;
        int n = nt * 8 + (ln >> 2);
        int kb = kt * 16 + (ln & 3) * 2;
        #pragma unroll
        for (int r = 0; r < 2; r++) {
            int k0 = kb + r * 8;
            float w0 = b1elem(k0, n, Wz, lzw, Wr, lrw, Wh, lhw);
            float w1 = b1elem(k0 + 1, n, Wz, lzw, Wr, lrw, Wh, lhw);
            uint32_t hi, lo;
            splith(w0, w1, hi, lo);
            d_fB1[((0 * 12 + nt) * 4 + kt) * 64 + ln * 2 + r] = hi;
            d_fB1[((1 * 12 + nt) * 4 + kt) * 64 + ln * 2 + r] = lo;
        }
    }
    // ---- Uh + Ln fragments (K=32 -> kt in {0,1}, N=32 -> nt in {0..3}) ----
    for (int i = tid; i < 4 * 2 * 32; i += 1024) {
        int nt = i >> 6;
        int kt = (i >> 5) & 1;
        int ln = i & 31;
        int n = nt * 8 + (ln >> 2);
        int kb = kt * 16 + (ln & 3) * 2;
        #pragma unroll
        for (int r = 0; r < 2; r++) {
            int k0 = kb + r * 8;
            float u0 = lhw[(32 + k0) * 32 + n];
            float u1 = lhw[(32 + k0 + 1) * 32 + n];
            float l0 = linw[k0 * 32 + n];
            float l1 = linw[(k0 + 1) * 32 + n];
            uint32_t hi, lo;
            splith(u0, u1, hi, lo);
            d_fUh[((0 * 4 + nt) * 2 + kt) * 64 + ln * 2 + r] = hi;
            d_fUh[((1 * 4 + nt) * 2 + kt) * 64 + ln * 2 + r] = lo;
            splith(l0, l1, hi, lo);
            d_fLn[((0 * 4 + nt) * 2 + kt) * 64 + ln * 2 + r] = hi;
            d_fLn[((1 * 4 + nt) * 2 + kt) * 64 + ln * 2 + r] = lo;
        }
    }
    // ---- folded biases + softmax ----
    if (tid < 96) {
        int g = tid >> 5; int jj = tid & 31;
        const float* bs = (g == 0) ? bz : (g == 1) ? br : bh;
        const float* ls = (g == 0) ? lzw : (g == 1) ? lrw : lhw;
        const float* lb = (g == 0) ? lzb : (g == 1) ? lrb : lhb;
        float s = lb[jj];
        for (int m = 0; m < 32; m++) s += bs[m] * ls[m * 32 + jj];
        d_bf[g * 32 + jj] = s;
    }
    if (tid == 0) {
        float mx = -1e30f;
        for (int i = 0; i < TT; i++) mx = fmaxf(mx, att[i]);
        float e[TT]; float sum = 0.f;
        for (int i = 0; i < TT; i++) { e[i] = expf(att[i] - mx); sum += e[i]; }
        for (int i = 0; i < TT; i++) d_probs[i] = e[i] / sum;
    }

    // ---- dinv ----
    for (int i = tid; i < NN; i += 1024) {
        float d = d_deg[i] + 1.0f;
        d_dinv[i] = rsqrtf(fmaxf(d, 1e-12f));
    }
    // ---- 3-level exclusive scan ----
    __shared__ int warpsum[32];
    int v[10];
    int s = 0;
    int base = tid * 10;
    if (tid < 1000) {
        #pragma unroll
        for (int u = 0; u < 10; u++) { v[u] = s; s += d_cnt[base + u]; }
    }
    int inc = s;
    #pragma unroll
    for (int o = 1; o < 32; o <<= 1) {
        int t = __shfl_up_sync(0xffffffffu, inc, o);
        if (lane >= o) inc += t;
    }
    if (lane == 31) warpsum[tid >> 5] = inc;
    __syncthreads();
    if (tid < 32) {
        int ws = warpsum[tid];
        int winc = ws;
        #pragma unroll
        for (int o = 1; o < 32; o <<= 1) {
            int t = __shfl_up_sync(0xffffffffu, winc, o);
            if (lane >= o) winc += t;
        }
        warpsum[tid] = winc - ws;
    }
    __syncthreads();
    int texcl = warpsum[tid >> 5] + inc - s;
    if (tid < 1000) {
        #pragma unroll
        for (int u = 0; u < 10; u++) d_rowptr[base + u] = texcl + v[u];
    }
    if (tid == 1000) d_rowptr[NN] = texcl;

    __syncthreads();
    for (int i = tid; i < NN; i += 1024) { d_deg[i] = 0.f; d_cnt[i] = 0; d_fill[i] = 0; }
}

__global__ void k_fill(const int* ei, const float* ew) {
    int e = blockIdx.x * blockDim.x + threadIdx.x;
    if (e >= EE) return;
    int r = ei[e];
    int c = ei[EE + e];
    int pos = d_rowptr[c] + atomicAdd(&d_fill[c], 1);
    float w = d_dinv[r] * ew[e] * d_dinv[c];
    d_csrp[pos] = make_int2(r, __float_as_int(w));
}

// -------- aggregation: gather in f32, store XA as fp16x2 (pair-packed) ----
__global__ void __launch_bounds__(256) k_agg(const float* __restrict__ x) {
    int w = (blockIdx.x * blockDim.x + threadIdx.x) >> 5;
    int lane = threadIdx.x & 31;
    if (w >= NN * 6) return;
    int g = w / NN;
    int n = w - g * NN;
    int half = lane >> 4;
    int fp = lane & 15;

    const ull* px = (const ull*)x;
    int sbase = g * 8 + half;
    long ofs0 = (long)(sbase + 0) * SL2 + fp;
    long ofs1 = (long)(sbase + 2) * SL2 + fp;
    long ofs2 = (long)(sbase + 4) * SL2 + fp;
    long ofs3 = (long)(sbase + 6) * SL2 + fp;

    float dn = d_dinv[n];
    ull selfw2 = splat2(dn * dn);
    ull acc0, acc1, acc2, acc3;
    {
        int r16 = n * 16;
        mul2(acc0, __ldg(px + ofs0 + r16), selfw2);
        mul2(acc1, __ldg(px + ofs1 + r16), selfw2);
        mul2(acc2, __ldg(px + ofs2 + r16), selfw2);
        mul2(acc3, __ldg(px + ofs3 + r16), selfw2);
    }
    int e0 = d_rowptr[n], e1 = d_rowptr[n + 1];
    int2 ed;
    if (e0 < e1) ed = __ldg(&d_csrp[e0]);
    for (int e = e0; e < e1; e++) {
        int2 edn;
        if (e + 1 < e1) edn = __ldg(&d_csrp[e + 1]);
        ull w2 = splat2(__int_as_float(ed.y));
        int r16 = ed.x * 16;
        ull v0 = __ldg(px + ofs0 + r16);
        ull v1 = __ldg(px + ofs1 + r16);
        ull v2 = __ldg(px + ofs2 + r16);
        ull v3 = __ldg(px + ofs3 + r16);
        fma2(acc0, v0, w2);
        fma2(acc1, v1, w2);
        fma2(acc2, v2, w2);
        fma2(acc3, v3, w2);
        ed = edn;
    }
    int n16 = n * 16 + fp;
    float2 f0 = unpk(acc0), f1 = unpk(acc1), f2 = unpk(acc2), f3 = unpk(acc3);
    __stcs(&d_XAh[(long)(sbase + 0) * SL2 + n16], packh(f0.x, f0.y));
    __stcs(&d_XAh[(long)(sbase + 2) * SL2 + n16], packh(f1.x, f1.y));
    __stcs(&d_XAh[(long)(sbase + 4) * SL2 + n16], packh(f2.x, f2.y));
    __stcs(&d_XAh[(long)(sbase + 6) * SL2 + n16], packh(f3.x, f3.y));
}

// ==================== warp-MMA GRU (fp16) ====================
// Warp owns 16 rows; h/hacc in registers for all 12 steps.
// HMMA per warp-step: z/r tiles (nt0-7) 1-term = 32; ah tiles (nt8-11)
// 1-term xa (8) + 1-term Uh (8) = 16. Total 48. (R14 showed B-weight
// rounding contributes ~nothing to output error.)
// Grid = 148*5 = 740 blocks (uniform 5/SM, kills the 4.22-blocks/SM
// wave-quantization tail of the 625-block launch); warps with
// task >= NTASK idle after the cooperative smem load.
__global__ void __launch_bounds__(128)
k_gruw(const float* __restrict__ linb, float* __restrict__ out) {
    __shared__ uint32_t sB1[6144];        // 24KB (hi terms used in loop; lo kept for Ln path layout parity)
    __shared__ uint32_t sUh[1024];        // 4KB
    __shared__ uint32_t sLn[1024];        // 4KB
    __shared__ float sbias[96];
    __shared__ float sprob[16];

    int tid = threadIdx.x;
    for (int i = tid; i < 6144; i += 128) sB1[i] = d_fB1[i];
    for (int i = tid; i < 1024; i += 128) { sUh[i] = d_fUh[i]; sLn[i] = d_fLn[i]; }
    if (tid < 96) sbias[tid] = d_bf[tid];
    if (tid < TT) sprob[tid] = d_probs[tid];
    __syncthreads();

    int lane = tid & 31;
    int wid = tid >> 5;
    int task = blockIdx.x * 4 + wid;
    if (task >= NTASK) return;                 // balanced launch: idle warps
    int m0 = task * 16;                        // NN%16==0 -> no batch straddle
    int b = m0 / NN;
    long basep = (long)b * (TT * SL2) + (long)(m0 - b * NN) * 16;   // pair units
    int r1 = lane >> 2;                        // fragment row (0..7)
    int c0q = lane & 3;                        // fragment col-pair index
    const uint32_t* xr1 = d_XAh + basep + (long)r1 * 16 + c0q;      // row r1
    const uint32_t* xr2 = xr1 + 8 * 16;                             // row r1+8
    int c0 = c0q * 2;

    // h, hacc in D-fragment layout: [nt(0..3)][i(0..3)]
    float h[16], hacc[16];
    #pragma unroll
    for (int j = 0; j < 16; j++) { h[j] = 0.f; hacc[j] = 0.f; }

    for (int t = 0; t < TT; t++) {
        // ---- A fragments: kt 0,1 pre-packed from XAh; kt 2,3 from h ----
        uint32_t a[4][4];
        #pragma unroll
        for (int kt = 0; kt < 2; kt++) {
            a[kt][0] = __ldg(xr1 + (long)t * SL2 + 4 * (2 * kt));
            a[kt][1] = __ldg(xr2 + (long)t * SL2 + 4 * (2 * kt));
            a[kt][2] = __ldg(xr1 + (long)t * SL2 + 4 * (2 * kt + 1));
            a[kt][3] = __ldg(xr2 + (long)t * SL2 + 4 * (2 * kt + 1));
        }
        #pragma unroll
        for (int kt = 2; kt < 4; kt++) {
            int hn = 2 * (kt - 2);
            a[kt][0] = packh(h[hn * 4 + 0],       h[hn * 4 + 1]);
            a[kt][1] = packh(h[hn * 4 + 2],       h[hn * 4 + 3]);
            a[kt][2] = packh(h[(hn + 1) * 4 + 0], h[(hn + 1) * 4 + 1]);
            a[kt][3] = packh(h[(hn + 1) * 4 + 2], h[(hn + 1) * 4 + 3]);
        }

        // ---- z, r gates: N-tiles 0..7, 1-term B ----
        float z[16], hr[16];
        #pragma unroll
        for (int nt = 0; nt < 8; nt++) {
            float d[4];
            #pragma unroll
            for (int i = 0; i < 4; i++) d[i] = sbias[8 * nt + c0 + (i & 1)];
            #pragma unroll
            for (int kt = 0; kt < 4; kt++) {
                uint2 bh = *(const uint2*)&sB1[((0 * 12 + nt) * 4 + kt) * 64 + lane * 2];
                mma16816(d, a[kt], bh.x, bh.y);
            }
            if (nt < 4) {
                #pragma unroll
                for (int i = 0; i < 4; i++)
                    z[nt * 4 + i] = 1.f / (1.f + __expf(-d[i]));
            } else {
                int hn = nt - 4;
                #pragma unroll
                for (int i = 0; i < 4; i++) {
                    float rg = 1.f / (1.f + __expf(-d[i]));
                    hr[hn * 4 + i] = h[hn * 4 + i] * rg;
                }
            }
        }
        // ---- hr fragments (1-term fp16, K=32 -> kt 0,1) ----
        uint32_t rfr[2][4];
        #pragma unroll
        for (int kt = 0; kt < 2; kt++) {
            int hn = 2 * kt;
            rfr[kt][0] = packh(hr[hn * 4 + 0],       hr[hn * 4 + 1]);
            rfr[kt][1] = packh(hr[hn * 4 + 2],       hr[hn * 4 + 3]);
            rfr[kt][2] = packh(hr[(hn + 1) * 4 + 0], hr[(hn + 1) * 4 + 1]);
            rfr[kt][3] = packh(hr[(hn + 1) * 4 + 2], hr[(hn + 1) * 4 + 3]);
        }

        // ---- ah tiles: N-tiles 8..11; 1-term xa (kt0,1) + 1-term Uh ----
        float pt = sprob[t];
        #pragma unroll
        for (int nt = 8; nt < 12; nt++) {
            float d[4];
            #pragma unroll
            for (int i = 0; i < 4; i++) d[i] = sbias[8 * nt + c0 + (i & 1)];
            #pragma unroll
            for (int kt = 0; kt < 2; kt++) {      // kt 2,3 multiply zeros: dropped
                uint2 bh = *(const uint2*)&sB1[((0 * 12 + nt) * 4 + kt) * 64 + lane * 2];
                mma16816(d, a[kt], bh.x, bh.y);
            }
            int un = nt - 8;
            #pragma unroll
            for (int kt = 0; kt < 2; kt++) {
                uint2 bh = *(const uint2*)&sUh[((0 * 4 + un) * 2 + kt) * 64 + lane * 2];
                mma16816(d, rfr[kt], bh.x, bh.y);
            }
            #pragma unroll
            for (int i = 0; i < 4; i++) {
                int j = un * 4 + i;
                float ht = 2.f / (1.f + __expf(-2.f * d[i])) - 1.f;   // tanh
                h[j] = z[j] * h[j] + (1.f - z[j]) * ht;
                hacc[j] += pt * h[j];
            }
        }
    }

    // ---- final: out = relu(hacc) @ lin_w + lin_b (2-term B, one-time) ----
    uint32_t rfr[2][4];
    #pragma unroll
    for (int kt = 0; kt < 2; kt++) {
        int hn = 2 * kt;
        rfr[kt][0] = packh(fmaxf(hacc[hn * 4 + 0], 0.f),       fmaxf(hacc[hn * 4 + 1], 0.f));
        rfr[kt][1] = packh(fmaxf(hacc[hn * 4 + 2], 0.f),       fmaxf(hacc[hn * 4 + 3], 0.f));
        rfr[kt][2] = packh(fmaxf(hacc[(hn + 1) * 4 + 0], 0.f), fmaxf(hacc[(hn + 1) * 4 + 1], 0.f));
        rfr[kt][3] = packh(fmaxf(hacc[(hn + 1) * 4 + 2], 0.f), fmaxf(hacc[(hn + 1) * 4 + 3], 0.f));
    }
    #pragma unroll
    for (int nt = 0; nt < 4; nt++) {
        float d[4];
        float lb0 = __ldg(&linb[8 * nt + c0]);
        float lb1 = __ldg(&linb[8 * nt + c0 + 1]);
        d[0] = lb0; d[1] = lb1; d[2] = lb0; d[3] = lb1;
        #pragma unroll
        for (int kt = 0; kt < 2; kt++) {
            uint2 bh = *(const uint2*)&sLn[((0 * 4 + nt) * 2 + kt) * 64 + lane * 2];
            uint2 bl = *(const uint2*)&sLn[((1 * 4 + nt) * 2 + kt) * 64 + lane * 2];
            mma16816(d, rfr[kt], bh.x, bh.y);
            mma16816(d, rfr[kt], bl.x, bl.y);
        }
        *(float2*)(out + (long)(m0 + r1) * 32 + 8 * nt + c0)     = make_float2(d[0], d[1]);
        *(float2*)(out + (long)(m0 + r1 + 8) * 32 + 8 * nt + c0) = make_float2(d[2], d[3]);
    }
}

extern "C" void kernel_launch(void* const* d_in, const int* in_sizes, int n_in,
                              void* d_out, int out_size) {
    const float* x  = (const float*)d_in[0];
    const int*   ei = (const int*)d_in[1];
    const float* ew = (const float*)d_in[2];

    int iWz, iBz, iLzw, iLzb, iWr, iBr, iLrw, iLrb, iWh, iBh, iLhw, iLhb;
    if (in_sizes[5] == 2048) {
        iWz = 3; iBz = 4; iLzw = 5;  iLzb = 6;
        iWr = 7; iBr = 8; iLrw = 9;  iLrb = 10;
        iWh = 11; iBh = 12; iLhw = 13; iLhb = 14;
    } else {
        iWz = 3; iBz = 4; iWr = 5; iBr = 6; iWh = 7; iBh = 8;
        iLzw = 9; iLzb = 10; iLrw = 11; iLrb = 12; iLhw = 13; iLhb = 14;
    }
    const float* Wz  = (const float*)d_in[iWz];
    const float* bz  = (const float*)d_in[iBz];
    const float* lzw = (const float*)d_in[iLzw];
    const float* lzb = (const float*)d_in[iLzb];
    const float* Wr  = (const float*)d_in[iWr];
    const float* br  = (const float*)d_in[iBr];
    const float* lrw = (const float*)d_in[iLrw];
    const float* lrb = (const float*)d_in[iLrb];
    const float* Wh  = (const float*)d_in[iWh];
    const float* bh  = (const float*)d_in[iBh];
    const float* lhw = (const float*)d_in[iLhw];
    const float* lhb = (const float*)d_in[iLhb];
    const float* att  = (const float*)d_in[15];
    const float* linw = (const float*)d_in[16];
    const float* linb = (const float*)d_in[17];
    float* out = (float*)d_out;

    k_degcnt<<<(EE + 255) / 256, 256>>>(ei, ew);                      // 1
    k_scan_prep<<<1, 1024>>>(att, Wz, bz, lzw, lzb, Wr, br, lrw, lrb,
                             Wh, bh, lhw, lhb, linw);                 // 2
    k_fill<<<(EE + 255) / 256, 256>>>(ei, ew);                        // 3
    {   // 4: aggregation (ncu captures this one)
        int threads = NN * 6 * 32;
        k_agg<<<(threads + 255) / 256, 256>>>(x);
    }
    // 5: balanced gru launch — 740 blocks = 5 per SM exactly
    k_gruw<<<740, 128>>>(linb, out);

    (void)n_in; (void)out_size;
}

// round 16
// speedup vs baseline: 1.2959x; 1.0275x over previous
#include <cuda_runtime.h>
#include <cuda_fp16.h>
#include <cstdint>

// Problem constants (fixed-shape problem)
#define BB 4
#define TT 12
#define NN 10000
#define FF 32
#define EE 160000
#define MM (BB*NN)          // 40000 rows
#define SLICES (BB*TT)      // 48
#define SL (NN*FF)          // 320000 elements per slice
#define SL2 (SL/2)          // slice stride in float2 / fp16x2-pair units
#define NTASK (MM/16)       // 2500 gru row-groups

typedef unsigned long long ull;

// -------- device scratch (static, no allocation; zero-initialized) --------
__device__ uint32_t d_XAh[SLICES * NN * 16];  // aggregated features, fp16x2 (30.7MB)
__device__ float d_deg[NN];
__device__ float d_dinv[NN];
__device__ int   d_cnt[NN];
__device__ int   d_fill[NN];
__device__ int   d_rowptr[NN + 1];
__device__ int2  d_csrp[EE];               // packed {src_row, weight_bits}
__device__ float d_bf[96];                 // folded biases z|r|h
__device__ float d_probs[TT];
// mma fragment-ordered f16x2 weights, 2-term (hi/lo): [term][nt][kt][lane][reg]
__device__ uint32_t d_fB1[2 * 12 * 4 * 32 * 2];   // gates B: K=64, N=96
__device__ uint32_t d_fUh[2 * 4 * 2 * 32 * 2];    // Uh:      K=32, N=32
__device__ uint32_t d_fLn[2 * 4 * 2 * 32 * 2];    // lin_w:   K=32, N=32

// ===================== f32x2 helpers (k_agg) =====================
__device__ __forceinline__ void fma2(ull& d, ull a, ull b) {
    asm("fma.rn.f32x2 %0, %1, %2, %0;" : "+l"(d) : "l"(a), "l"(b));
}
__device__ __forceinline__ void mul2(ull& d, ull a, ull b) {
    asm("mul.rn.f32x2 %0, %1, %2;" : "=l"(d) : "l"(a), "l"(b));
}
__device__ __forceinline__ ull splat2(float w) {
    ull r; asm("mov.b64 %0, {%1, %1};" : "=l"(r) : "f"(w)); return r;
}
__device__ __forceinline__ float2 unpk(ull a) {
    float2 f; asm("mov.b64 {%0, %1}, %2;" : "=f"(f.x), "=f"(f.y) : "l"(a)); return f;
}

// ===================== fp16 pack/split helpers =====================
__device__ __forceinline__ uint32_t packh(float a, float b) {
    __half2 h = __floats2half2_rn(a, b);        // x=a (low), y=b (high)
    return *(uint32_t*)&h;
}
__device__ __forceinline__ void splith(float a, float b, uint32_t& hi, uint32_t& lo) {
    hi = packh(a, b);
    __half2 hh = *(__half2*)&hi;
    lo = packh(a - __half2float(hh.x), b - __half2float(hh.y));
}
// mma.sync m16n8k16 row.col fp16 -> f32, D += A*B
__device__ __forceinline__ void mma16816(float* d, const uint32_t* a,
                                         uint32_t b0, uint32_t b1) {
    asm("mma.sync.aligned.m16n8k16.row.col.f32.f16.f16.f32 "
        "{%0,%1,%2,%3}, {%4,%5,%6,%7}, {%8,%9}, {%0,%1,%2,%3};"
        : "+f"(d[0]), "+f"(d[1]), "+f"(d[2]), "+f"(d[3])
        : "r"(a[0]), "r"(a[1]), "r"(a[2]), "r"(a[3]), "r"(b0), "r"(b1));
}

// -------- degree/count accumulation --------
__global__ void k_degcnt(const int* ei, const float* ew) {
    int e = blockIdx.x * blockDim.x + threadIdx.x;
    if (e >= EE) return;
    int col = ei[EE + e];
    atomicAdd(&d_deg[col], ew[e]);
    atomicAdd(&d_cnt[col], 1);
}

// single-block: parallel shared fold + fragment build + dinv + scan +
// bias fold + softmax + counter re-zero.
__global__ void k_scan_prep(const float* att,
                            const float* Wz, const float* bz, const float* lzw, const float* lzb,
                            const float* Wr, const float* br, const float* lrw, const float* lrb,
                            const float* Wh, const float* bh, const float* lhw, const float* lhb,
                            const float* linw) {
    __shared__ float sFold[64 * 96];      // 24KB: B1[k][j] = [W' ; Uz|Ur|0]
    int tid = threadIdx.x;
    int lane = tid & 31;

    // ---- parallel fold into shared: k=tid>>5 (0..31), j=tid&31 ----
    {
        int k = tid >> 5, j = tid & 31;
        const float* Ws[3] = {Wz, Wr, Wh};
        const float* ls[3] = {lzw, lrw, lhw};
        #pragma unroll
        for (int g = 0; g < 3; g++) {
            float s = 0.f;
            #pragma unroll
            for (int m = 0; m < 32; m++) s += Ws[g][k * 32 + m] * ls[g][m * 32 + j];
            sFold[k * 96 + g * 32 + j] = s;
        }
        sFold[(32 + k) * 96 +  0 + j] = lzw[(32 + k) * 32 + j];  // Uz
        sFold[(32 + k) * 96 + 32 + j] = lrw[(32 + k) * 32 + j];  // Ur
        sFold[(32 + k) * 96 + 64 + j] = 0.f;                     // zeros (Wh h-cols)
    }
    __syncthreads();

    // ---- B1 fragments (fp16 hi/lo) from shared fold ----
    for (int i = tid; i < 12 * 4 * 32; i += 1024) {
        int nt = i >> 7;
        int kt = (i >> 5) & 3;
        int ln = i & 31;
        int n = nt * 8 + (ln >> 2);
        int kb = kt * 16 + (ln & 3) * 2;
        #pragma unroll
        for (int r = 0; r < 2; r++) {
            int k0 = kb + r * 8;
            float w0 = sFold[k0 * 96 + n];
            float w1 = sFold[(k0 + 1) * 96 + n];
            uint32_t hi, lo;
            splith(w0, w1, hi, lo);
            d_fB1[((0 * 12 + nt) * 4 + kt) * 64 + ln * 2 + r] = hi;
            d_fB1[((1 * 12 + nt) * 4 + kt) * 64 + ln * 2 + r] = lo;
        }
    }
    // ---- Uh + Ln fragments (direct reads, no fold needed) ----
    for (int i = tid; i < 4 * 2 * 32; i += 1024) {
        int nt = i >> 6;
        int kt = (i >> 5) & 1;
        int ln = i & 31;
        int n = nt * 8 + (ln >> 2);
        int kb = kt * 16 + (ln & 3) * 2;
        #pragma unroll
        for (int r = 0; r < 2; r++) {
            int k0 = kb + r * 8;
            float u0 = lhw[(32 + k0) * 32 + n];
            float u1 = lhw[(32 + k0 + 1) * 32 + n];
            float l0 = linw[k0 * 32 + n];
            float l1 = linw[(k0 + 1) * 32 + n];
            uint32_t hi, lo;
            splith(u0, u1, hi, lo);
            d_fUh[((0 * 4 + nt) * 2 + kt) * 64 + ln * 2 + r] = hi;
            d_fUh[((1 * 4 + nt) * 2 + kt) * 64 + ln * 2 + r] = lo;
            splith(l0, l1, hi, lo);
            d_fLn[((0 * 4 + nt) * 2 + kt) * 64 + ln * 2 + r] = hi;
            d_fLn[((1 * 4 + nt) * 2 + kt) * 64 + ln * 2 + r] = lo;
        }
    }
    // ---- folded biases + softmax ----
    if (tid < 96) {
        int g = tid >> 5; int jj = tid & 31;
        const float* bs = (g == 0) ? bz : (g == 1) ? br : bh;
        const float* ls = (g == 0) ? lzw : (g == 1) ? lrw : lhw;
        const float* lb = (g == 0) ? lzb : (g == 1) ? lrb : lhb;
        float s = lb[jj];
        for (int m = 0; m < 32; m++) s += bs[m] * ls[m * 32 + jj];
        d_bf[g * 32 + jj] = s;
    }
    if (tid == 0) {
        float mx = -1e30f;
        for (int i = 0; i < TT; i++) mx = fmaxf(mx, att[i]);
        float e[TT]; float sum = 0.f;
        for (int i = 0; i < TT; i++) { e[i] = expf(att[i] - mx); sum += e[i]; }
        for (int i = 0; i < TT; i++) d_probs[i] = e[i] / sum;
    }

    // ---- dinv ----
    for (int i = tid; i < NN; i += 1024) {
        float d = d_deg[i] + 1.0f;
        d_dinv[i] = rsqrtf(fmaxf(d, 1e-12f));
    }
    // ---- 3-level exclusive scan ----
    __shared__ int warpsum[32];
    int v[10];
    int s = 0;
    int base = tid * 10;
    if (tid < 1000) {
        #pragma unroll
        for (int u = 0; u < 10; u++) { v[u] = s; s += d_cnt[base + u]; }
    }
    int inc = s;
    #pragma unroll
    for (int o = 1; o < 32; o <<= 1) {
        int t = __shfl_up_sync(0xffffffffu, inc, o);
        if (lane >= o) inc += t;
    }
    if (lane == 31) warpsum[tid >> 5] = inc;
    __syncthreads();
    if (tid < 32) {
        int ws = warpsum[tid];
        int winc = ws;
        #pragma unroll
        for (int o = 1; o < 32; o <<= 1) {
            int t = __shfl_up_sync(0xffffffffu, winc, o);
            if (lane >= o) winc += t;
        }
        warpsum[tid] = winc - ws;
    }
    __syncthreads();
    int texcl = warpsum[tid >> 5] + inc - s;
    if (tid < 1000) {
        #pragma unroll
        for (int u = 0; u < 10; u++) d_rowptr[base + u] = texcl + v[u];
    }
    if (tid == 1000) d_rowptr[NN] = texcl;

    __syncthreads();
    for (int i = tid; i < NN; i += 1024) { d_deg[i] = 0.f; d_cnt[i] = 0; d_fill[i] = 0; }
}

__global__ void k_fill(const int* ei, const float* ew) {
    int e = blockIdx.x * blockDim.x + threadIdx.x;
    if (e >= EE) return;
    int r = ei[e];
    int c = ei[EE + e];
    int pos = d_rowptr[c] + atomicAdd(&d_fill[c], 1);
    float w = d_dinv[r] * ew[e] * d_dinv[c];
    d_csrp[pos] = make_int2(r, __float_as_int(w));
}

// -------- aggregation: gather in f32, store XA as fp16x2 (pair-packed) ----
__global__ void __launch_bounds__(256) k_agg(const float* __restrict__ x) {
    int w = (blockIdx.x * blockDim.x + threadIdx.x) >> 5;
    int lane = threadIdx.x & 31;
    if (w >= NN * 6) return;
    int g = w / NN;
    int n = w - g * NN;
    int half = lane >> 4;
    int fp = lane & 15;

    const ull* px = (const ull*)x;
    int sbase = g * 8 + half;
    long ofs0 = (long)(sbase + 0) * SL2 + fp;
    long ofs1 = (long)(sbase + 2) * SL2 + fp;
    long ofs2 = (long)(sbase + 4) * SL2 + fp;
    long ofs3 = (long)(sbase + 6) * SL2 + fp;

    float dn = d_dinv[n];
    ull selfw2 = splat2(dn * dn);
    ull acc0, acc1, acc2, acc3;
    {
        int r16 = n * 16;
        mul2(acc0, __ldg(px + ofs0 + r16), selfw2);
        mul2(acc1, __ldg(px + ofs1 + r16), selfw2);
        mul2(acc2, __ldg(px + ofs2 + r16), selfw2);
        mul2(acc3, __ldg(px + ofs3 + r16), selfw2);
    }
    int e0 = d_rowptr[n], e1 = d_rowptr[n + 1];
    int2 ed;
    if (e0 < e1) ed = __ldg(&d_csrp[e0]);
    for (int e = e0; e < e1; e++) {
        int2 edn;
        if (e + 1 < e1) edn = __ldg(&d_csrp[e + 1]);
        ull w2 = splat2(__int_as_float(ed.y));
        int r16 = ed.x * 16;
        ull v0 = __ldg(px + ofs0 + r16);
        ull v1 = __ldg(px + ofs1 + r16);
        ull v2 = __ldg(px + ofs2 + r16);
        ull v3 = __ldg(px + ofs3 + r16);
        fma2(acc0, v0, w2);
        fma2(acc1, v1, w2);
        fma2(acc2, v2, w2);
        fma2(acc3, v3, w2);
        ed = edn;
    }
    int n16 = n * 16 + fp;
    float2 f0 = unpk(acc0), f1 = unpk(acc1), f2 = unpk(acc2), f3 = unpk(acc3);
    __stcs(&d_XAh[(long)(sbase + 0) * SL2 + n16], packh(f0.x, f0.y));
    __stcs(&d_XAh[(long)(sbase + 2) * SL2 + n16], packh(f1.x, f1.y));
    __stcs(&d_XAh[(long)(sbase + 4) * SL2 + n16], packh(f2.x, f2.y));
    __stcs(&d_XAh[(long)(sbase + 6) * SL2 + n16], packh(f3.x, f3.y));
}

// ==================== warp-MMA GRU (fp16) ====================
// Warp owns 16 rows; h/hacc in registers for all 12 steps.
// 48 HMMA/warp-step. Biases hoisted to registers (saves 48 LDS/step).
__global__ void __launch_bounds__(128)
k_gruw(const float* __restrict__ linb, float* __restrict__ out) {
    __shared__ uint32_t sB1[6144];        // 24KB
    __shared__ uint32_t sUh[1024];        // 4KB
    __shared__ uint32_t sLn[1024];        // 4KB
    __shared__ float sbias[96];
    __shared__ float sprob[16];

    int tid = threadIdx.x;
    for (int i = tid; i < 6144; i += 128) sB1[i] = d_fB1[i];
    for (int i = tid; i < 1024; i += 128) { sUh[i] = d_fUh[i]; sLn[i] = d_fLn[i]; }
    if (tid < 96) sbias[tid] = d_bf[tid];
    if (tid < TT) sprob[tid] = d_probs[tid];
    __syncthreads();

    int lane = tid & 31;
    int wid = tid >> 5;
    int task = blockIdx.x * 4 + wid;
    if (task >= NTASK) return;
    int m0 = task * 16;                        // NN%16==0 -> no batch straddle
    int b = m0 / NN;
    long basep = (long)b * (TT * SL2) + (long)(m0 - b * NN) * 16;   // pair units
    int r1 = lane >> 2;                        // fragment row (0..7)
    int c0q = lane & 3;                        // fragment col-pair index
    const uint32_t* xr1 = d_XAh + basep + (long)r1 * 16 + c0q;      // row r1
    const uint32_t* xr2 = xr1 + 8 * 16;                             // row r1+8
    int c0 = c0q * 2;

    // hoist biases + probs to registers
    float bias0[12], bias1[12];
    #pragma unroll
    for (int nt = 0; nt < 12; nt++) {
        bias0[nt] = sbias[8 * nt + c0];
        bias1[nt] = sbias[8 * nt + c0 + 1];
    }

    float h[16], hacc[16];
    #pragma unroll
    for (int j = 0; j < 16; j++) { h[j] = 0.f; hacc[j] = 0.f; }

    for (int t = 0; t < TT; t++) {
        // ---- A fragments: kt 0,1 pre-packed from XAh; kt 2,3 from h ----
        uint32_t a[4][4];
        #pragma unroll
        for (int kt = 0; kt < 2; kt++) {
            a[kt][0] = __ldg(xr1 + (long)t * SL2 + 4 * (2 * kt));
            a[kt][1] = __ldg(xr2 + (long)t * SL2 + 4 * (2 * kt));
            a[kt][2] = __ldg(xr1 + (long)t * SL2 + 4 * (2 * kt + 1));
            a[kt][3] = __ldg(xr2 + (long)t * SL2 + 4 * (2 * kt + 1));
        }
        #pragma unroll
        for (int kt = 2; kt < 4; kt++) {
            int hn = 2 * (kt - 2);
            a[kt][0] = packh(h[hn * 4 + 0],       h[hn * 4 + 1]);
            a[kt][1] = packh(h[hn * 4 + 2],       h[hn * 4 + 3]);
            a[kt][2] = packh(h[(hn + 1) * 4 + 0], h[(hn + 1) * 4 + 1]);
            a[kt][3] = packh(h[(hn + 1) * 4 + 2], h[(hn + 1) * 4 + 3]);
        }

        // ---- z, r gates: N-tiles 0..7, 1-term B ----
        float z[16], hr[16];
        #pragma unroll
        for (int nt = 0; nt < 8; nt++) {
            float d[4];
            d[0] = bias0[nt]; d[1] = bias1[nt]; d[2] = bias0[nt]; d[3] = bias1[nt];
            #pragma unroll
            for (int kt = 0; kt < 4; kt++) {
                uint2 bh = *(const uint2*)&sB1[((0 * 12 + nt) * 4 + kt) * 64 + lane * 2];
                mma16816(d, a[kt], bh.x, bh.y);
            }
            if (nt < 4) {
                #pragma unroll
                for (int i = 0; i < 4; i++)
                    z[nt * 4 + i] = 1.f / (1.f + __expf(-d[i]));
            } else {
                int hn = nt - 4;
                #pragma unroll
                for (int i = 0; i < 4; i++) {
                    float rg = 1.f / (1.f + __expf(-d[i]));
                    hr[hn * 4 + i] = h[hn * 4 + i] * rg;
                }
            }
        }
        // ---- hr fragments (1-term fp16, K=32 -> kt 0,1) ----
        uint32_t rfr[2][4];
        #pragma unroll
        for (int kt = 0; kt < 2; kt++) {
            int hn = 2 * kt;
            rfr[kt][0] = packh(hr[hn * 4 + 0],       hr[hn * 4 + 1]);
            rfr[kt][1] = packh(hr[hn * 4 + 2],       hr[hn * 4 + 3]);
            rfr[kt][2] = packh(hr[(hn + 1) * 4 + 0], hr[(hn + 1) * 4 + 1]);
            rfr[kt][3] = packh(hr[(hn + 1) * 4 + 2], hr[(hn + 1) * 4 + 3]);
        }

        // ---- ah tiles: N-tiles 8..11; 1-term xa (kt0,1) + 1-term Uh ----
        float pt = sprob[t];
        #pragma unroll
        for (int nt = 8; nt < 12; nt++) {
            float d[4];
            d[0] = bias0[nt]; d[1] = bias1[nt]; d[2] = bias0[nt]; d[3] = bias1[nt];
            #pragma unroll
            for (int kt = 0; kt < 2; kt++) {      // kt 2,3 multiply zeros: dropped
                uint2 bh = *(const uint2*)&sB1[((0 * 12 + nt) * 4 + kt) * 64 + lane * 2];
                mma16816(d, a[kt], bh.x, bh.y);
            }
            int un = nt - 8;
            #pragma unroll
            for (int kt = 0; kt < 2; kt++) {
                uint2 bh = *(const uint2*)&sUh[((0 * 4 + un) * 2 + kt) * 64 + lane * 2];
                mma16816(d, rfr[kt], bh.x, bh.y);
            }
            #pragma unroll
            for (int i = 0; i < 4; i++) {
                int j = un * 4 + i;
                float ht = 2.f / (1.f + __expf(-2.f * d[i])) - 1.f;   // tanh
                h[j] = z[j] * h[j] + (1.f - z[j]) * ht;
                hacc[j] += pt * h[j];
            }
        }
    }

    // ---- final: out = relu(hacc) @ lin_w + lin_b (2-term B, one-time) ----
    uint32_t rfr[2][4];
    #pragma unroll
    for (int kt = 0; kt < 2; kt++) {
        int hn = 2 * kt;
        rfr[kt][0] = packh(fmaxf(hacc[hn * 4 + 0], 0.f),       fmaxf(hacc[hn * 4 + 1], 0.f));
        rfr[kt][1] = packh(fmaxf(hacc[hn * 4 + 2], 0.f),       fmaxf(hacc[hn * 4 + 3], 0.f));
        rfr[kt][2] = packh(fmaxf(hacc[(hn + 1) * 4 + 0], 0.f), fmaxf(hacc[(hn + 1) * 4 + 1], 0.f));
        rfr[kt][3] = packh(fmaxf(hacc[(hn + 1) * 4 + 2], 0.f), fmaxf(hacc[(hn + 1) * 4 + 3], 0.f));
    }
    #pragma unroll
    for (int nt = 0; nt < 4; nt++) {
        float d[4];
        float lb0 = __ldg(&linb[8 * nt + c0]);
        float lb1 = __ldg(&linb[8 * nt + c0 + 1]);
        d[0] = lb0; d[1] = lb1; d[2] = lb0; d[3] = lb1;
        #pragma unroll
        for (int kt = 0; kt < 2; kt++) {
            uint2 bh = *(const uint2*)&sLn[((0 * 4 + nt) * 2 + kt) * 64 + lane * 2];
            uint2 bl = *(const uint2*)&sLn[((1 * 4 + nt) * 2 + kt) * 64 + lane * 2];
            mma16816(d, rfr[kt], bh.x, bh.y);
            mma16816(d, rfr[kt], bl.x, bl.y);
        }
        *(float2*)(out + (long)(m0 + r1) * 32 + 8 * nt + c0)     = make_float2(d[0], d[1]);
        *(float2*)(out + (long)(m0 + r1 + 8) * 32 + 8 * nt + c0) = make_float2(d[2], d[3]);
    }
}

extern "C" void kernel_launch(void* const* d_in, const int* in_sizes, int n_in,
                              void* d_out, int out_size) {
    const float* x  = (const float*)d_in[0];
    const int*   ei = (const int*)d_in[1];
    const float* ew = (const float*)d_in[2];

    int iWz, iBz, iLzw, iLzb, iWr, iBr, iLrw, iLrb, iWh, iBh, iLhw, iLhb;
    if (in_sizes[5] == 2048) {
        iWz = 3; iBz = 4; iLzw = 5;  iLzb = 6;
        iWr = 7; iBr = 8; iLrw = 9;  iLrb = 10;
        iWh = 11; iBh = 12; iLhw = 13; iLhb = 14;
    } else {
        iWz = 3; iBz = 4; iWr = 5; iBr = 6; iWh = 7; iBh = 8;
        iLzw = 9; iLzb = 10; iLrw = 11; iLrb = 12; iLhw = 13; iLhb = 14;
    }
    const float* Wz  = (const float*)d_in[iWz];
    const float* bz  = (const float*)d_in[iBz];
    const float* lzw = (const float*)d_in[iLzw];
    const float* lzb = (const float*)d_in[iLzb];
    const float* Wr  = (const float*)d_in[iWr];
    const float* br  = (const float*)d_in[iBr];
    const float* lrw = (const float*)d_in[iLrw];
    const float* lrb = (const float*)d_in[iLrb];
    const float* Wh  = (const float*)d_in[iWh];
    const float* bh  = (const float*)d_in[iBh];
    const float* lhw = (const float*)d_in[iLhw];
    const float* lhb = (const float*)d_in[iLhb];
    const float* att  = (const float*)d_in[15];
    const float* linw = (const float*)d_in[16];
    const float* linb = (const float*)d_in[17];
    float* out = (float*)d_out;

    k_degcnt<<<(EE + 255) / 256, 256>>>(ei, ew);                      // 1
    k_scan_prep<<<1, 1024>>>(att, Wz, bz, lzw, lzb, Wr, br, lrw, lrb,
                             Wh, bh, lhw, lhb, linw);                 // 2
    k_fill<<<(EE + 255) / 256, 256>>>(ei, ew);                        // 3
    {   // 4: aggregation (ncu captures this one)
        int threads = NN * 6 * 32;
        k_agg<<<(threads + 255) / 256, 256>>>(x);
    }
    k_gruw<<<740, 128>>>(linb, out);                                  // 5

    (void)n_in; (void)out_size;
}